// round 7
// baseline (speedup 1.0000x reference)
#include <cuda_runtime.h>
#include <cuda_bf16.h>
#include <cstdint>
#include <cstddef>

#define DDIM 4096
#define BATCH 2048
#define CAND_CAP (1u << 23)

// ---------------------------------------------------------------------------
// Device-global scratch
// ---------------------------------------------------------------------------
__device__ unsigned int g_hist16[65536];
__device__ unsigned int g_cand[CAND_CAP];
__device__ unsigned int g_cand_cnt;
__device__ unsigned int g_prefix;   // selected 16-bit prefix
__device__ unsigned int g_krem;     // remaining rank within prefix bin
__device__ float        g_thr;

__device__ __align__(128) __nv_bfloat16 g_W1hi[(size_t)DDIM * DDIM];
__device__ __align__(128) __nv_bfloat16 g_W1lo[(size_t)DDIM * DDIM];
__device__ __align__(128) __nv_bfloat16 g_W2hi[(size_t)DDIM * DDIM];
__device__ __align__(128) __nv_bfloat16 g_W2lo[(size_t)DDIM * DDIM];
__device__ __align__(128) __nv_bfloat16 g_W3hi[(size_t)DDIM * DDIM];
__device__ __align__(128) __nv_bfloat16 g_W3lo[(size_t)DDIM * DDIM];
__device__ __align__(128) __nv_bfloat16 g_Xhi[(size_t)BATCH * DDIM];
__device__ __align__(128) __nv_bfloat16 g_Xlo[(size_t)BATCH * DDIM];
__device__ __align__(128) __nv_bfloat16 g_H1hi[(size_t)BATCH * DDIM];
__device__ __align__(128) __nv_bfloat16 g_H1lo[(size_t)BATCH * DDIM];
__device__ __align__(128) __nv_bfloat16 g_H2hi[(size_t)BATCH * DDIM];
__device__ __align__(128) __nv_bfloat16 g_H2lo[(size_t)BATCH * DDIM];
__device__ float g_B1[DDIM];
__device__ float g_B2[DDIM];
__device__ float g_B3[DDIM];

// ---------------------------------------------------------------------------
// Radix select v2: ONE 16-bit histogram pass + compaction + tiny finish.
// key = (u & 0x80000000) ? ~u : (u | 0x80000000)   (ascending float order)
// ---------------------------------------------------------------------------
__device__ __forceinline__ unsigned int f2key(float f)
{
    unsigned int u = __float_as_uint(f);
    return (u & 0x80000000u) ? ~u : (u | 0x80000000u);
}

__global__ void rs16_init()
{
    int i = blockIdx.x * blockDim.x + threadIdx.x;
    const int stride = gridDim.x * blockDim.x;
    for (; i < 65536; i += stride) g_hist16[i] = 0u;
    if (blockIdx.x == 0 && threadIdx.x == 0) g_cand_cnt = 0u;
}

__global__ void rs16_hist(const float* __restrict__ p, int n4)
{
    const float4* __restrict__ p4 = (const float4*)p;
    int i = blockIdx.x * blockDim.x + threadIdx.x;
    const int stride = gridDim.x * blockDim.x;
    const int lane = threadIdx.x & 31;
    for (; i < n4; i += stride) {
        float4 v = p4[i];
        float arr[4] = {v.x, v.y, v.z, v.w};
        #pragma unroll
        for (int c = 0; c < 4; c++) {
            unsigned int bin = f2key(arr[c]) >> 16;
            unsigned int amask = __activemask();
            unsigned int peers = __match_any_sync(amask, bin);
            if (lane == __ffs(peers) - 1)
                atomicAdd(&g_hist16[bin], (unsigned int)__popc(peers));
        }
    }
}

// Single block, 256 threads: find 16-bit prefix bin containing rank k.
__global__ void rs16_scan(unsigned int k)
{
    __shared__ unsigned int s[256];
    const int t = threadIdx.x;
    const int base = t * 256;
    unsigned int sum = 0;
    for (int i = 0; i < 256; i++) sum += g_hist16[base + i];
    s[t] = sum;
    __syncthreads();
    #pragma unroll
    for (int off = 1; off < 256; off <<= 1) {
        unsigned int add = (t >= off) ? s[t - off] : 0u;
        __syncthreads();
        s[t] += add;
        __syncthreads();
    }
    const unsigned int inc = s[t];
    const unsigned int exc = inc - sum;
    if (k >= exc && k < inc) {
        unsigned int run = exc;
        for (int i = 0; i < 256; i++) {
            unsigned int c = g_hist16[base + i];
            if (k < run + c) { g_prefix = (unsigned int)(base + i);
                               g_krem = k - run; break; }
            run += c;
        }
    }
}

// Gather all keys whose top 16 bits match g_prefix.
__global__ void rs_compact(const float* __restrict__ p, int n4)
{
    const unsigned int pref = g_prefix;
    const float4* __restrict__ p4 = (const float4*)p;
    int i = blockIdx.x * blockDim.x + threadIdx.x;
    const int stride = gridDim.x * blockDim.x;
    const int lane = threadIdx.x & 31;
    for (; i < n4; i += stride) {
        float4 v = p4[i];
        float arr[4] = {v.x, v.y, v.z, v.w};
        #pragma unroll
        for (int c = 0; c < 4; c++) {
            unsigned int key = f2key(arr[c]);
            bool m = (key >> 16) == pref;
            unsigned int amask = __activemask();
            unsigned int bal = __ballot_sync(amask, m);
            if (m) {
                int leader = __ffs(bal) - 1;
                unsigned int base = 0;
                if (lane == leader)
                    base = atomicAdd(&g_cand_cnt, (unsigned int)__popc(bal));
                base = __shfl_sync(bal, base, leader);
                unsigned int idx = base + __popc(bal & ((1u << lane) - 1u));
                if (idx < CAND_CAP) g_cand[idx] = key;
            }
        }
    }
}

// Single block: finish low 16 bits over the (tiny) candidate set.
__global__ void rs_final()
{
    __shared__ unsigned int sh[256];
    __shared__ unsigned int s_b2, s_k2;
    const int tid = threadIdx.x;   // 1024
    unsigned int n = g_cand_cnt;
    if (n > CAND_CAP) n = CAND_CAP;
    const unsigned int k = g_krem;

    if (tid < 256) sh[tid] = 0u;
    __syncthreads();
    for (unsigned int i = tid; i < n; i += 1024)
        atomicAdd(&sh[(g_cand[i] >> 8) & 0xffu], 1u);
    __syncthreads();
    if (tid == 0) {
        unsigned int run = 0;
        for (int b = 0; b < 256; b++) {
            unsigned int c = sh[b];
            if (k < run + c) { s_b2 = (unsigned int)b; s_k2 = k - run; break; }
            run += c;
        }
    }
    __syncthreads();
    const unsigned int b2 = s_b2, k2 = s_k2;
    if (tid < 256) sh[tid] = 0u;
    __syncthreads();
    for (unsigned int i = tid; i < n; i += 1024) {
        unsigned int key = g_cand[i];
        if (((key >> 8) & 0xffu) == b2) atomicAdd(&sh[key & 0xffu], 1u);
    }
    __syncthreads();
    if (tid == 0) {
        unsigned int run = 0;
        for (int b = 0; b < 256; b++) {
            unsigned int c = sh[b];
            if (k2 < run + c) {
                unsigned int key = (g_prefix << 16) | (b2 << 8) | (unsigned int)b;
                unsigned int u = (key & 0x80000000u) ? (key ^ 0x80000000u) : ~key;
                g_thr = __uint_as_float(u);
                break;
            }
            run += c;
        }
    }
}

// ---------------------------------------------------------------------------
// hi/lo split helpers + mask kernels
// ---------------------------------------------------------------------------
__device__ __forceinline__ void split2(float f0, float f1,
                                       unsigned int& h, unsigned int& l)
{
    __nv_bfloat16 h0 = __float2bfloat16(f0);
    __nv_bfloat16 h1 = __float2bfloat16(f1);
    __nv_bfloat16 l0 = __float2bfloat16(f0 - __bfloat162float(h0));
    __nv_bfloat16 l1 = __float2bfloat16(f1 - __bfloat162float(h1));
    h = (unsigned int)__bfloat16_as_ushort(h0) |
        ((unsigned int)__bfloat16_as_ushort(h1) << 16);
    l = (unsigned int)__bfloat16_as_ushort(l0) |
        ((unsigned int)__bfloat16_as_ushort(l1) << 16);
}

__global__ void mask_split(const float* __restrict__ w,
                           const float* __restrict__ s,
                           __nv_bfloat16* __restrict__ hi,
                           __nv_bfloat16* __restrict__ lo, int n4)
{
    const float thr = g_thr;
    const float4* __restrict__ w4 = (const float4*)w;
    const float4* __restrict__ s4 = (const float4*)s;
    uint2* __restrict__ h2 = (uint2*)hi;
    uint2* __restrict__ l2 = (uint2*)lo;
    int i = blockIdx.x * blockDim.x + threadIdx.x;
    const int stride = gridDim.x * blockDim.x;
    for (; i < n4; i += stride) {
        float4 wv = w4[i];
        float4 sv = s4[i];
        float f0 = (sv.x >= thr) ? wv.x : 0.0f;
        float f1 = (sv.y >= thr) ? wv.y : 0.0f;
        float f2 = (sv.z >= thr) ? wv.z : 0.0f;
        float f3 = (sv.w >= thr) ? wv.w : 0.0f;
        uint2 hu, lu;
        split2(f0, f1, hu.x, lu.x);
        split2(f2, f3, hu.y, lu.y);
        h2[i] = hu;
        l2[i] = lu;
    }
}

__global__ void split_plain(const float* __restrict__ in,
                            __nv_bfloat16* __restrict__ hi,
                            __nv_bfloat16* __restrict__ lo, int n4)
{
    const float4* __restrict__ p4 = (const float4*)in;
    uint2* __restrict__ h2 = (uint2*)hi;
    uint2* __restrict__ l2 = (uint2*)lo;
    int i = blockIdx.x * blockDim.x + threadIdx.x;
    const int stride = gridDim.x * blockDim.x;
    for (; i < n4; i += stride) {
        float4 v = p4[i];
        uint2 hu, lu;
        split2(v.x, v.y, hu.x, lu.x);
        split2(v.z, v.w, hu.y, lu.y);
        h2[i] = hu;
        l2[i] = lu;
    }
}

__global__ void mask_mul(const float* __restrict__ w,
                         const float* __restrict__ s,
                         float* __restrict__ out, int n4)
{
    const float thr = g_thr;
    const float4* __restrict__ w4 = (const float4*)w;
    const float4* __restrict__ s4 = (const float4*)s;
    float4* __restrict__ o4 = (float4*)out;
    int i = blockIdx.x * blockDim.x + threadIdx.x;
    const int stride = gridDim.x * blockDim.x;
    for (; i < n4; i += stride) {
        float4 wv = w4[i];
        float4 sv = s4[i];
        float4 r;
        r.x = (sv.x >= thr) ? wv.x : 0.0f;
        r.y = (sv.y >= thr) ? wv.y : 0.0f;
        r.z = (sv.z >= thr) ? wv.z : 0.0f;
        r.w = (sv.w >= thr) ? wv.w : 0.0f;
        o4[i] = r;
    }
}

// ---------------------------------------------------------------------------
// sm_100-baseline tensor-core primitives: cp.async + ldmatrix + mma.sync
// ---------------------------------------------------------------------------
__device__ __forceinline__ uint32_t smem_u32(const void* p)
{
    uint32_t a;
    asm("{ .reg .u64 t; cvta.to.shared.u64 t, %1; cvt.u32.u64 %0, t; }"
        : "=r"(a) : "l"(p));
    return a;
}

__device__ __forceinline__ void cpasync16(uint32_t dst, const void* src)
{
    asm volatile("cp.async.cg.shared.global [%0], [%1], 16;"
                 :: "r"(dst), "l"(src) : "memory");
}
#define CP_COMMIT() asm volatile("cp.async.commit_group;" ::: "memory")
#define CP_WAIT_1() asm volatile("cp.async.wait_group 1;" ::: "memory")

__device__ __forceinline__ void ldsm4(uint32_t& r0, uint32_t& r1,
                                      uint32_t& r2, uint32_t& r3, uint32_t a)
{
    asm volatile("ldmatrix.sync.aligned.m8n8.x4.shared.b16 {%0,%1,%2,%3}, [%4];"
                 : "=r"(r0), "=r"(r1), "=r"(r2), "=r"(r3) : "r"(a));
}

__device__ __forceinline__ void mma16816(float* c,
                                         uint32_t a0, uint32_t a1,
                                         uint32_t a2, uint32_t a3,
                                         uint32_t b0, uint32_t b1)
{
    asm volatile(
        "mma.sync.aligned.m16n8k16.row.col.f32.bf16.bf16.f32 "
        "{%0,%1,%2,%3}, {%4,%5,%6,%7}, {%8,%9}, {%0,%1,%2,%3};"
        : "+f"(c[0]), "+f"(c[1]), "+f"(c[2]), "+f"(c[3])
        : "r"(a0), "r"(a1), "r"(a2), "r"(a3), "r"(b0), "r"(b1));
}

// ---------------------------------------------------------------------------
// bf16x3 HMMA GEMM: C[128x128 tile] = A[M,K] @ B[N,K]^T + bias (opt ReLU)
// 3-stage cp.async pipeline; 8 warps 2(M)x4(N); warp tile 64x32; BK=32.
// Fragment-reuse inner loop: ah/bh/bl loaded once, al loaded late, bh reused.
// ---------------------------------------------------------------------------
#define BM 128
#define BN 128
#define BK 32
#define GSTAGES 3
#define STG_B (4 * BM * BK * 2)        /* 32768 bytes per stage */
#define GSMEM  (GSTAGES * STG_B)       /* 98304 */

template<int RELU, int OUT_BF16>
__global__ void __launch_bounds__(256) gemm_hmma(
    const __nv_bfloat16* __restrict__ Ah, const __nv_bfloat16* __restrict__ Al,
    const __nv_bfloat16* __restrict__ Bh, const __nv_bfloat16* __restrict__ Bl,
    const float* __restrict__ bias,
    float* __restrict__ outf,
    __nv_bfloat16* __restrict__ outhi,
    __nv_bfloat16* __restrict__ outlo)
{
    extern __shared__ __align__(128) char smem[];
    const uint32_t sbase = smem_u32(smem);
    const int tid  = threadIdx.x;
    const int lane = tid & 31;
    const int wid  = tid >> 5;
    const int wm   = wid >> 2;          // 0..1
    const int wn   = wid & 3;           // 0..3
    const int bx   = blockIdx.x;        // N tile
    const int by   = blockIdx.y;        // M tile
    const int K    = DDIM;

    // --- global->shared load mapping: each thread owns 8 x 16B chunks ---
    const int lrow = tid >> 2;          // 0..63
    const int lch  = tid & 3;           // 16B chunk within 64B row
    const uint32_t d0 = (uint32_t)lrow * 64 + (uint32_t)((lch ^ (lrow & 3)) << 4);

    const int rowA = by * BM;
    const int rowB = bx * BN;
    const __nv_bfloat16* sAh0 = Ah + (size_t)(rowA + lrow) * K + lch * 8;
    const __nv_bfloat16* sAh1 = Ah + (size_t)(rowA + lrow + 64) * K + lch * 8;
    const __nv_bfloat16* sAl0 = Al + (size_t)(rowA + lrow) * K + lch * 8;
    const __nv_bfloat16* sAl1 = Al + (size_t)(rowA + lrow + 64) * K + lch * 8;
    const __nv_bfloat16* sBh0 = Bh + (size_t)(rowB + lrow) * K + lch * 8;
    const __nv_bfloat16* sBh1 = Bh + (size_t)(rowB + lrow + 64) * K + lch * 8;
    const __nv_bfloat16* sBl0 = Bl + (size_t)(rowB + lrow) * K + lch * 8;
    const __nv_bfloat16* sBl1 = Bl + (size_t)(rowB + lrow + 64) * K + lch * 8;

    #define LOAD_STAGE(stg, kt) do {                                          \
        const uint32_t s0 = sbase + (uint32_t)(stg) * STG_B + d0;             \
        const size_t ko = (size_t)(kt) * BK;                                  \
        cpasync16(s0,          sAh0 + ko);                                    \
        cpasync16(s0 + 4096,   sAh1 + ko);                                    \
        cpasync16(s0 + 8192,   sAl0 + ko);                                    \
        cpasync16(s0 + 12288,  sAl1 + ko);                                    \
        cpasync16(s0 + 16384,  sBh0 + ko);                                    \
        cpasync16(s0 + 20480,  sBh1 + ko);                                    \
        cpasync16(s0 + 24576,  sBl0 + ko);                                    \
        cpasync16(s0 + 28672,  sBl1 + ko);                                    \
    } while (0)

    float c[4][4][4];
    #pragma unroll
    for (int i = 0; i < 4; i++)
        #pragma unroll
        for (int j = 0; j < 4; j++)
            #pragma unroll
            for (int q = 0; q < 4; q++) c[i][j][q] = 0.0f;

    const int NT = K / BK;              // 128

    LOAD_STAGE(0, 0); CP_COMMIT();
    LOAD_STAGE(1, 1); CP_COMMIT();

    const int fr = lane & 15;           // row within 16-row tile
    const int fh = lane >> 4;           // 0/1 -> +16B column chunk

    for (int t = 0; t < NT; t++) {
        CP_WAIT_1();
        __syncthreads();

        const int lt = t + GSTAGES - 1;
        if (lt < NT) LOAD_STAGE(lt % GSTAGES, lt);
        CP_COMMIT();

        const uint32_t sb = sbase + (uint32_t)(t % GSTAGES) * STG_B;

        #pragma unroll
        for (int kk = 0; kk < 2; kk++) {
            const int chb = kk * 2 + fh;   // 16B chunk index 0..3

            // per-tile swizzled row offsets (computed once per kk)
            uint32_t aoff[4], boff[2];
            #pragma unroll
            for (int mi = 0; mi < 4; mi++) {
                const int row = wm * 64 + mi * 16 + fr;
                aoff[mi] = (uint32_t)row * 64 + (uint32_t)((chb ^ (row & 3)) << 4);
            }
            #pragma unroll
            for (int nj = 0; nj < 2; nj++) {
                const int row = wn * 32 + nj * 16 + fr;
                boff[nj] = (uint32_t)row * 64 + (uint32_t)((chb ^ (row & 3)) << 4);
            }

            // load Ah, Bh, Bl fragments once
            uint32_t ah[4][4], bh[2][4], bl[2][4];
            #pragma unroll
            for (int mi = 0; mi < 4; mi++)
                ldsm4(ah[mi][0], ah[mi][1], ah[mi][2], ah[mi][3], sb + aoff[mi]);
            #pragma unroll
            for (int nj = 0; nj < 2; nj++) {
                ldsm4(bh[nj][0], bh[nj][1], bh[nj][2], bh[nj][3],
                      sb + 16384u + boff[nj]);
                ldsm4(bl[nj][0], bl[nj][1], bl[nj][2], bl[nj][3],
                      sb + 24576u + boff[nj]);
            }

            // pass hh: Ah x Bh
            #pragma unroll
            for (int mi = 0; mi < 4; mi++) {
                mma16816(c[mi][0], ah[mi][0], ah[mi][1], ah[mi][2], ah[mi][3],
                         bh[0][0], bh[0][2]);
                mma16816(c[mi][1], ah[mi][0], ah[mi][1], ah[mi][2], ah[mi][3],
                         bh[0][1], bh[0][3]);
                mma16816(c[mi][2], ah[mi][0], ah[mi][1], ah[mi][2], ah[mi][3],
                         bh[1][0], bh[1][2]);
                mma16816(c[mi][3], ah[mi][0], ah[mi][1], ah[mi][2], ah[mi][3],
                         bh[1][1], bh[1][3]);
            }
            // pass hl: Ah x Bl
            #pragma unroll
            for (int mi = 0; mi < 4; mi++) {
                mma16816(c[mi][0], ah[mi][0], ah[mi][1], ah[mi][2], ah[mi][3],
                         bl[0][0], bl[0][2]);
                mma16816(c[mi][1], ah[mi][0], ah[mi][1], ah[mi][2], ah[mi][3],
                         bl[0][1], bl[0][3]);
                mma16816(c[mi][2], ah[mi][0], ah[mi][1], ah[mi][2], ah[mi][3],
                         bl[1][0], bl[1][2]);
                mma16816(c[mi][3], ah[mi][0], ah[mi][1], ah[mi][2], ah[mi][3],
                         bl[1][1], bl[1][3]);
            }
            // pass lh: Al x Bh (load Al now, reuse Bh fragments)
            #pragma unroll
            for (int mi = 0; mi < 4; mi++) {
                uint32_t al0, al1, al2, al3;
                ldsm4(al0, al1, al2, al3, sb + 8192u + aoff[mi]);
                mma16816(c[mi][0], al0, al1, al2, al3, bh[0][0], bh[0][2]);
                mma16816(c[mi][1], al0, al1, al2, al3, bh[0][1], bh[0][3]);
                mma16816(c[mi][2], al0, al1, al2, al3, bh[1][0], bh[1][2]);
                mma16816(c[mi][3], al0, al1, al2, al3, bh[1][1], bh[1][3]);
            }
        }
    }

    // --- epilogue: bias (+ReLU), then fp32 store or bf16 hi/lo re-split ---
    const int q   = lane >> 2;          // 0..7
    const int rp  = lane & 3;           // column pair
    const int m0g = by * BM + wm * 64;
    const int n0g = bx * BN + wn * 32;

    #pragma unroll
    for (int mi = 0; mi < 4; mi++) {
        #pragma unroll
        for (int ni = 0; ni < 4; ni++) {
            const int col = n0g + ni * 8 + rp * 2;
            const float bv0 = __ldg(bias + col);
            const float bv1 = __ldg(bias + col + 1);
            float v0 = c[mi][ni][0] + bv0;
            float v1 = c[mi][ni][1] + bv1;
            float v2 = c[mi][ni][2] + bv0;
            float v3 = c[mi][ni][3] + bv1;
            if (RELU) {
                v0 = fmaxf(v0, 0.0f); v1 = fmaxf(v1, 0.0f);
                v2 = fmaxf(v2, 0.0f); v3 = fmaxf(v3, 0.0f);
            }
            const int r0 = m0g + mi * 16 + q;
            const int r1 = r0 + 8;
            if (OUT_BF16) {
                unsigned int h, l;
                split2(v0, v1, h, l);
                *(unsigned int*)(outhi + (size_t)r0 * DDIM + col) = h;
                *(unsigned int*)(outlo + (size_t)r0 * DDIM + col) = l;
                split2(v2, v3, h, l);
                *(unsigned int*)(outhi + (size_t)r1 * DDIM + col) = h;
                *(unsigned int*)(outlo + (size_t)r1 * DDIM + col) = l;
            } else {
                *(float2*)(outf + (size_t)r0 * DDIM + col) = make_float2(v0, v1);
                *(float2*)(outf + (size_t)r1 * DDIM + col) = make_float2(v2, v3);
            }
        }
    }
    #undef LOAD_STAGE
}

// ---------------------------------------------------------------------------
// kernel_launch
// ---------------------------------------------------------------------------
extern "C" void kernel_launch(void* const* d_in, const int* in_sizes, int n_in,
                              void* d_out, int out_size)
{
    const float* x   = (const float*)d_in[0];
    const float* w1  = (const float*)d_in[1];
    const float* b1  = (const float*)d_in[2];
    const float* w2  = (const float*)d_in[3];
    const float* b2  = (const float*)d_in[4];
    const float* w3  = (const float*)d_in[5];
    const float* b3  = (const float*)d_in[6];
    const float* sw1 = (const float*)d_in[7];
    const float* sb1 = (const float*)d_in[8];
    const float* sw2 = (const float*)d_in[9];
    const float* sb2 = (const float*)d_in[10];
    const float* sw3 = (const float*)d_in[11];
    const float* sb3 = (const float*)d_in[12];
    float* out = (float*)d_out;

    const int M = in_sizes[0] / DDIM;   // 2048

    long long total = 0;
    for (int i = 7; i <= 12; i++) total += (long long)in_sizes[i];
    const unsigned int j = (unsigned int)(total / 2);

    const int nW4 = (DDIM * DDIM) / 4;
    const int nB4 = DDIM / 4;
    const int nX4 = (M * DDIM) / 4;

    // --- 1) exact global threshold: 1-pass 16-bit hist + compact + finish ---
    rs16_init<<<64, 1024>>>();
    rs16_hist<<<1024, 256>>>(sw1, nW4);
    rs16_hist<<<1024, 256>>>(sw2, nW4);
    rs16_hist<<<1024, 256>>>(sw3, nW4);
    rs16_hist<<<4,    256>>>(sb1, nB4);
    rs16_hist<<<4,    256>>>(sb2, nB4);
    rs16_hist<<<4,    256>>>(sb3, nB4);
    rs16_scan<<<1, 256>>>(j);
    rs_compact<<<1024, 256>>>(sw1, nW4);
    rs_compact<<<1024, 256>>>(sw2, nW4);
    rs_compact<<<1024, 256>>>(sw3, nW4);
    rs_compact<<<4,    256>>>(sb1, nB4);
    rs_compact<<<4,    256>>>(sb2, nB4);
    rs_compact<<<4,    256>>>(sb3, nB4);
    rs_final<<<1, 1024>>>();

    // --- scratch symbol addresses ---
    __nv_bfloat16 *pW1h, *pW1l, *pW2h, *pW2l, *pW3h, *pW3l;
    __nv_bfloat16 *pXh, *pXl, *pH1h, *pH1l, *pH2h, *pH2l;
    float *pB1, *pB2, *pB3;
    cudaGetSymbolAddress((void**)&pW1h, g_W1hi);
    cudaGetSymbolAddress((void**)&pW1l, g_W1lo);
    cudaGetSymbolAddress((void**)&pW2h, g_W2hi);
    cudaGetSymbolAddress((void**)&pW2l, g_W2lo);
    cudaGetSymbolAddress((void**)&pW3h, g_W3hi);
    cudaGetSymbolAddress((void**)&pW3l, g_W3lo);
    cudaGetSymbolAddress((void**)&pXh,  g_Xhi);
    cudaGetSymbolAddress((void**)&pXl,  g_Xlo);
    cudaGetSymbolAddress((void**)&pH1h, g_H1hi);
    cudaGetSymbolAddress((void**)&pH1l, g_H1lo);
    cudaGetSymbolAddress((void**)&pH2h, g_H2hi);
    cudaGetSymbolAddress((void**)&pH2l, g_H2lo);
    cudaGetSymbolAddress((void**)&pB1,  g_B1);
    cudaGetSymbolAddress((void**)&pB2,  g_B2);
    cudaGetSymbolAddress((void**)&pB3,  g_B3);

    // --- 2) masked weights -> bf16 hi/lo ; masked biases fp32 ; split x ---
    mask_split<<<1024, 256>>>(w1, sw1, pW1h, pW1l, nW4);
    mask_split<<<1024, 256>>>(w2, sw2, pW2h, pW2l, nW4);
    mask_split<<<1024, 256>>>(w3, sw3, pW3h, pW3l, nW4);
    mask_mul<<<4, 256>>>(b1, sb1, pB1, nB4);
    mask_mul<<<4, 256>>>(b2, sb2, pB2, nB4);
    mask_mul<<<4, 256>>>(b3, sb3, pB3, nB4);
    split_plain<<<1024, 256>>>(x, pXh, pXl, nX4);

    // --- 3) three dependent bf16x3 HMMA GEMMs ---
    cudaFuncSetAttribute(gemm_hmma<1, 1>,
                         cudaFuncAttributeMaxDynamicSharedMemorySize, GSMEM);
    cudaFuncSetAttribute(gemm_hmma<0, 0>,
                         cudaFuncAttributeMaxDynamicSharedMemorySize, GSMEM);

    dim3 grid(DDIM / BN, M / BM);       // (32, 16)
    gemm_hmma<1, 1><<<grid, 256, GSMEM>>>(pXh,  pXl,  pW1h, pW1l, pB1,
                                          nullptr, pH1h, pH1l);
    gemm_hmma<1, 1><<<grid, 256, GSMEM>>>(pH1h, pH1l, pW2h, pW2l, pB2,
                                          nullptr, pH2h, pH2l);
    gemm_hmma<0, 0><<<grid, 256, GSMEM>>>(pH2h, pH2l, pW3h, pW3l, pB3,
                                          out, nullptr, nullptr);

    (void)n_in; (void)out_size;
}

// round 8
// speedup vs baseline: 1.8707x; 1.8707x over previous
#include <cuda_runtime.h>
#include <cuda_bf16.h>
#include <cuda_fp16.h>
#include <cstdint>
#include <cstddef>

#define DDIM 4096
#define BATCH 2048

// ---------------------------------------------------------------------------
// Device-global scratch
// ---------------------------------------------------------------------------
__device__ unsigned int g_hist[256];
__device__ unsigned int g_prefix;
__device__ unsigned int g_krem;
__device__ float        g_thr;

__device__ __align__(128) __half g_W1h[(size_t)DDIM * DDIM];
__device__ __align__(128) __half g_W2h[(size_t)DDIM * DDIM];
__device__ __align__(128) __half g_W3h[(size_t)DDIM * DDIM];
__device__ __align__(128) __half g_Xhi[(size_t)BATCH * DDIM];
__device__ __align__(128) __half g_Xlo[(size_t)BATCH * DDIM];
__device__ __align__(128) __half g_H1hi[(size_t)BATCH * DDIM];
__device__ __align__(128) __half g_H1lo[(size_t)BATCH * DDIM];
__device__ __align__(128) __half g_H2hi[(size_t)BATCH * DDIM];
__device__ __align__(128) __half g_H2lo[(size_t)BATCH * DDIM];
__device__ float g_B1[DDIM];
__device__ float g_B2[DDIM];
__device__ float g_B3[DDIM];

// ---------------------------------------------------------------------------
// Radix select (R6-verified): exact j-th smallest of all score values.
// key = (u & 0x80000000) ? ~u : (u | 0x80000000)   (ascending float order)
// ---------------------------------------------------------------------------
__global__ void rs_init(unsigned int k)
{
    int t = threadIdx.x;
    if (t < 256) g_hist[t] = 0u;
    if (t == 0) { g_prefix = 0u; g_krem = k; }
}

__global__ void rs_hist(const float* __restrict__ p, int n4, int shift)
{
    __shared__ unsigned int sh[256];
    for (int i = threadIdx.x; i < 256; i += blockDim.x) sh[i] = 0u;
    __syncthreads();
    const unsigned int pref = g_prefix;
    const float4* __restrict__ p4 = (const float4*)p;
    int i = blockIdx.x * blockDim.x + threadIdx.x;
    const int stride = gridDim.x * blockDim.x;
    for (; i < n4; i += stride) {
        float4 v = p4[i];
        float arr[4] = {v.x, v.y, v.z, v.w};
        #pragma unroll
        for (int c = 0; c < 4; c++) {
            unsigned int u   = __float_as_uint(arr[c]);
            unsigned int key = (u & 0x80000000u) ? ~u : (u | 0x80000000u);
            bool match = (shift == 24) || (((key ^ pref) >> (shift + 8)) == 0u);
            unsigned int bin = (key >> shift) & 0xffu;
            unsigned int tag   = match ? bin : (256u + (threadIdx.x & 31u));
            unsigned int amask = __activemask();
            unsigned int peers = __match_any_sync(amask, tag);
            if (match) {
                int lead = __ffs(peers) - 1;
                if ((int)(threadIdx.x & 31u) == lead)
                    atomicAdd(&sh[bin], (unsigned int)__popc(peers));
            }
        }
    }
    __syncthreads();
    for (int i2 = threadIdx.x; i2 < 256; i2 += blockDim.x) {
        unsigned int cv = sh[i2];
        if (cv) atomicAdd(&g_hist[i2], cv);
    }
}

__global__ void rs_scan(int shift)
{
    __shared__ unsigned int s[256];
    const int t = threadIdx.x;
    unsigned int c = g_hist[t];
    g_hist[t] = 0u;
    s[t] = c;
    __syncthreads();
    #pragma unroll
    for (int off = 1; off < 256; off <<= 1) {
        unsigned int add = (t >= off) ? s[t - off] : 0u;
        __syncthreads();
        s[t] += add;
        __syncthreads();
    }
    const unsigned int inc = s[t];
    const unsigned int exc = inc - c;
    const unsigned int k   = g_krem;
    if (k >= exc && k < inc) {
        unsigned int newpref = g_prefix | ((unsigned int)t << shift);
        g_prefix = newpref;
        g_krem   = k - exc;
        if (shift == 0) {
            unsigned int u = (newpref & 0x80000000u) ? (newpref ^ 0x80000000u)
                                                     : ~newpref;
            g_thr = __uint_as_float(u);
        }
    }
}

// ---------------------------------------------------------------------------
// fp16 split helpers + mask kernels
// ---------------------------------------------------------------------------
__device__ __forceinline__ void split2h(float f0, float f1,
                                        unsigned int& h, unsigned int& l)
{
    __half h0 = __float2half_rn(f0);
    __half h1 = __float2half_rn(f1);
    __half l0 = __float2half_rn(f0 - __half2float(h0));
    __half l1 = __float2half_rn(f1 - __half2float(h1));
    h = (unsigned int)__half_as_ushort(h0) |
        ((unsigned int)__half_as_ushort(h1) << 16);
    l = (unsigned int)__half_as_ushort(l0) |
        ((unsigned int)__half_as_ushort(l1) << 16);
}

// masked weight -> single fp16
__global__ void mask_half(const float* __restrict__ w,
                          const float* __restrict__ s,
                          __half* __restrict__ out, int n4)
{
    const float thr = g_thr;
    const float4* __restrict__ w4 = (const float4*)w;
    const float4* __restrict__ s4 = (const float4*)s;
    uint2* __restrict__ o2 = (uint2*)out;
    int i = blockIdx.x * blockDim.x + threadIdx.x;
    const int stride = gridDim.x * blockDim.x;
    for (; i < n4; i += stride) {
        float4 wv = w4[i];
        float4 sv = s4[i];
        float f0 = (sv.x >= thr) ? wv.x : 0.0f;
        float f1 = (sv.y >= thr) ? wv.y : 0.0f;
        float f2 = (sv.z >= thr) ? wv.z : 0.0f;
        float f3 = (sv.w >= thr) ? wv.w : 0.0f;
        uint2 o;
        o.x = (unsigned int)__half_as_ushort(__float2half_rn(f0)) |
              ((unsigned int)__half_as_ushort(__float2half_rn(f1)) << 16);
        o.y = (unsigned int)__half_as_ushort(__float2half_rn(f2)) |
              ((unsigned int)__half_as_ushort(__float2half_rn(f3)) << 16);
        o2[i] = o;
    }
}

// plain fp32 -> fp16 hi/lo (for x)
__global__ void split_plain_h(const float* __restrict__ in,
                              __half* __restrict__ hi,
                              __half* __restrict__ lo, int n4)
{
    const float4* __restrict__ p4 = (const float4*)in;
    uint2* __restrict__ h2 = (uint2*)hi;
    uint2* __restrict__ l2 = (uint2*)lo;
    int i = blockIdx.x * blockDim.x + threadIdx.x;
    const int stride = gridDim.x * blockDim.x;
    for (; i < n4; i += stride) {
        float4 v = p4[i];
        uint2 hu, lu;
        split2h(v.x, v.y, hu.x, lu.x);
        split2h(v.z, v.w, hu.y, lu.y);
        h2[i] = hu;
        l2[i] = lu;
    }
}

// masked bias (fp32, tiny)
__global__ void mask_mul(const float* __restrict__ w,
                         const float* __restrict__ s,
                         float* __restrict__ out, int n4)
{
    const float thr = g_thr;
    const float4* __restrict__ w4 = (const float4*)w;
    const float4* __restrict__ s4 = (const float4*)s;
    float4* __restrict__ o4 = (float4*)out;
    int i = blockIdx.x * blockDim.x + threadIdx.x;
    const int stride = gridDim.x * blockDim.x;
    for (; i < n4; i += stride) {
        float4 wv = w4[i];
        float4 sv = s4[i];
        float4 r;
        r.x = (sv.x >= thr) ? wv.x : 0.0f;
        r.y = (sv.y >= thr) ? wv.y : 0.0f;
        r.z = (sv.z >= thr) ? wv.z : 0.0f;
        r.w = (sv.w >= thr) ? wv.w : 0.0f;
        o4[i] = r;
    }
}

// ---------------------------------------------------------------------------
// cp.async + ldmatrix + mma.sync (fp16)
// ---------------------------------------------------------------------------
__device__ __forceinline__ uint32_t smem_u32(const void* p)
{
    uint32_t a;
    asm("{ .reg .u64 t; cvta.to.shared.u64 t, %1; cvt.u32.u64 %0, t; }"
        : "=r"(a) : "l"(p));
    return a;
}

__device__ __forceinline__ void cpasync16(uint32_t dst, const void* src)
{
    asm volatile("cp.async.cg.shared.global [%0], [%1], 16;"
                 :: "r"(dst), "l"(src) : "memory");
}
#define CP_COMMIT() asm volatile("cp.async.commit_group;" ::: "memory")
#define CP_WAIT_1() asm volatile("cp.async.wait_group 1;" ::: "memory")

__device__ __forceinline__ void ldsm4(uint32_t& r0, uint32_t& r1,
                                      uint32_t& r2, uint32_t& r3, uint32_t a)
{
    asm volatile("ldmatrix.sync.aligned.m8n8.x4.shared.b16 {%0,%1,%2,%3}, [%4];"
                 : "=r"(r0), "=r"(r1), "=r"(r2), "=r"(r3) : "r"(a));
}

__device__ __forceinline__ void mma16816h(float* c,
                                          uint32_t a0, uint32_t a1,
                                          uint32_t a2, uint32_t a3,
                                          uint32_t b0, uint32_t b1)
{
    asm volatile(
        "mma.sync.aligned.m16n8k16.row.col.f32.f16.f16.f32 "
        "{%0,%1,%2,%3}, {%4,%5,%6,%7}, {%8,%9}, {%0,%1,%2,%3};"
        : "+f"(c[0]), "+f"(c[1]), "+f"(c[2]), "+f"(c[3])
        : "r"(a0), "r"(a1), "r"(a2), "r"(a3), "r"(b0), "r"(b1));
}

// ---------------------------------------------------------------------------
// fp16 2-pass HMMA GEMM: C = Ahi@B^T + Alo@B^T + bias (opt ReLU)
// A hi/lo fp16 (K-contig), B single fp16 (K-contig). 3-stage cp.async.
// 256 threads = 8 warps 2(M) x 4(N); warp tile 64x32; BK=32.
// Stage layout: Ahi[128][32] @0, Alo @8192, B[128][32] @16384 (24 KB/stage).
// ---------------------------------------------------------------------------
#define BM 128
#define BN 128
#define BK 32
#define GSTAGES 3
#define STG_B (3 * BM * BK * 2)        /* 24576 bytes per stage */
#define GSMEM  (GSTAGES * STG_B)       /* 73728 */

template<int RELU, int OUT_HALF>
__global__ void __launch_bounds__(256) gemm_hmma(
    const __half* __restrict__ Ah, const __half* __restrict__ Al,
    const __half* __restrict__ B,
    const float* __restrict__ bias,
    float* __restrict__ outf,
    __half* __restrict__ outhi,
    __half* __restrict__ outlo)
{
    extern __shared__ __align__(128) char smem[];
    const uint32_t sbase = smem_u32(smem);
    const int tid  = threadIdx.x;
    const int lane = tid & 31;
    const int wid  = tid >> 5;
    const int wm   = wid >> 2;          // 0..1
    const int wn   = wid & 3;           // 0..3
    const int bx   = blockIdx.x;        // N tile
    const int by   = blockIdx.y;        // M tile
    const int K    = DDIM;

    // global->shared mapping: each thread owns 6 x 16B chunks per stage
    const int lrow = tid >> 2;          // 0..63
    const int lch  = tid & 3;           // 16B chunk within 64B row
    const uint32_t d0 = (uint32_t)lrow * 64 + (uint32_t)((lch ^ (lrow & 3)) << 4);

    const int rowA = by * BM;
    const int rowB = bx * BN;
    const __half* sAh0 = Ah + (size_t)(rowA + lrow) * K + lch * 8;
    const __half* sAh1 = Ah + (size_t)(rowA + lrow + 64) * K + lch * 8;
    const __half* sAl0 = Al + (size_t)(rowA + lrow) * K + lch * 8;
    const __half* sAl1 = Al + (size_t)(rowA + lrow + 64) * K + lch * 8;
    const __half* sB0  = B  + (size_t)(rowB + lrow) * K + lch * 8;
    const __half* sB1  = B  + (size_t)(rowB + lrow + 64) * K + lch * 8;

    #define LOAD_STAGE(stg, kt) do {                                          \
        const uint32_t s0 = sbase + (uint32_t)(stg) * STG_B + d0;             \
        const size_t ko = (size_t)(kt) * BK;                                  \
        cpasync16(s0,          sAh0 + ko);                                    \
        cpasync16(s0 + 4096,   sAh1 + ko);                                    \
        cpasync16(s0 + 8192,   sAl0 + ko);                                    \
        cpasync16(s0 + 12288,  sAl1 + ko);                                    \
        cpasync16(s0 + 16384,  sB0  + ko);                                    \
        cpasync16(s0 + 20480,  sB1  + ko);                                    \
    } while (0)

    float c[4][4][4];
    #pragma unroll
    for (int i = 0; i < 4; i++)
        #pragma unroll
        for (int j = 0; j < 4; j++)
            #pragma unroll
            for (int q = 0; q < 4; q++) c[i][j][q] = 0.0f;

    const int NT = K / BK;              // 128

    LOAD_STAGE(0, 0); CP_COMMIT();
    LOAD_STAGE(1, 1); CP_COMMIT();

    const int fr = lane & 15;           // row within 16-row tile
    const int fh = lane >> 4;           // 0/1 -> +16B column chunk

    for (int t = 0; t < NT; t++) {
        CP_WAIT_1();
        __syncthreads();

        const int lt = t + GSTAGES - 1;
        if (lt < NT) LOAD_STAGE(lt % GSTAGES, lt);
        CP_COMMIT();

        const uint32_t sb = sbase + (uint32_t)(t % GSTAGES) * STG_B;

        #pragma unroll
        for (int kk = 0; kk < 2; kk++) {
            const int chb = kk * 2 + fh;   // 16B chunk index 0..3

            uint32_t aoff[4], boff[2];
            #pragma unroll
            for (int mi = 0; mi < 4; mi++) {
                const int row = wm * 64 + mi * 16 + fr;
                aoff[mi] = (uint32_t)row * 64 + (uint32_t)((chb ^ (row & 3)) << 4);
            }
            #pragma unroll
            for (int nj = 0; nj < 2; nj++) {
                const int row = wn * 32 + nj * 16 + fr;
                boff[nj] = (uint32_t)row * 64 + (uint32_t)((chb ^ (row & 3)) << 4);
            }

            // B fragments loaded once, reused for both passes
            uint32_t b[2][4];
            #pragma unroll
            for (int nj = 0; nj < 2; nj++)
                ldsm4(b[nj][0], b[nj][1], b[nj][2], b[nj][3],
                      sb + 16384u + boff[nj]);

            // pass 1: Ahi x B
            #pragma unroll
            for (int mi = 0; mi < 4; mi++) {
                uint32_t a0, a1, a2, a3;
                ldsm4(a0, a1, a2, a3, sb + aoff[mi]);
                mma16816h(c[mi][0], a0, a1, a2, a3, b[0][0], b[0][2]);
                mma16816h(c[mi][1], a0, a1, a2, a3, b[0][1], b[0][3]);
                mma16816h(c[mi][2], a0, a1, a2, a3, b[1][0], b[1][2]);
                mma16816h(c[mi][3], a0, a1, a2, a3, b[1][1], b[1][3]);
            }
            // pass 2: Alo x B (reuse B fragments)
            #pragma unroll
            for (int mi = 0; mi < 4; mi++) {
                uint32_t a0, a1, a2, a3;
                ldsm4(a0, a1, a2, a3, sb + 8192u + aoff[mi]);
                mma16816h(c[mi][0], a0, a1, a2, a3, b[0][0], b[0][2]);
                mma16816h(c[mi][1], a0, a1, a2, a3, b[0][1], b[0][3]);
                mma16816h(c[mi][2], a0, a1, a2, a3, b[1][0], b[1][2]);
                mma16816h(c[mi][3], a0, a1, a2, a3, b[1][1], b[1][3]);
            }
        }
    }

    // --- epilogue: bias (+ReLU), then fp32 store or fp16 hi/lo re-split ---
    const int q   = lane >> 2;          // 0..7
    const int rp  = lane & 3;           // column pair
    const int m0g = by * BM + wm * 64;
    const int n0g = bx * BN + wn * 32;

    #pragma unroll
    for (int mi = 0; mi < 4; mi++) {
        #pragma unroll
        for (int ni = 0; ni < 4; ni++) {
            const int col = n0g + ni * 8 + rp * 2;
            const float bv0 = __ldg(bias + col);
            const float bv1 = __ldg(bias + col + 1);
            float v0 = c[mi][ni][0] + bv0;
            float v1 = c[mi][ni][1] + bv1;
            float v2 = c[mi][ni][2] + bv0;
            float v3 = c[mi][ni][3] + bv1;
            if (RELU) {
                v0 = fmaxf(v0, 0.0f); v1 = fmaxf(v1, 0.0f);
                v2 = fmaxf(v2, 0.0f); v3 = fmaxf(v3, 0.0f);
            }
            const int r0 = m0g + mi * 16 + q;
            const int r1 = r0 + 8;
            if (OUT_HALF) {
                unsigned int h, l;
                split2h(v0, v1, h, l);
                *(unsigned int*)(outhi + (size_t)r0 * DDIM + col) = h;
                *(unsigned int*)(outlo + (size_t)r0 * DDIM + col) = l;
                split2h(v2, v3, h, l);
                *(unsigned int*)(outhi + (size_t)r1 * DDIM + col) = h;
                *(unsigned int*)(outlo + (size_t)r1 * DDIM + col) = l;
            } else {
                *(float2*)(outf + (size_t)r0 * DDIM + col) = make_float2(v0, v1);
                *(float2*)(outf + (size_t)r1 * DDIM + col) = make_float2(v2, v3);
            }
        }
    }
    #undef LOAD_STAGE
}

// ---------------------------------------------------------------------------
// kernel_launch
// ---------------------------------------------------------------------------
extern "C" void kernel_launch(void* const* d_in, const int* in_sizes, int n_in,
                              void* d_out, int out_size)
{
    const float* x   = (const float*)d_in[0];
    const float* w1  = (const float*)d_in[1];
    const float* b1  = (const float*)d_in[2];
    const float* w2  = (const float*)d_in[3];
    const float* b2  = (const float*)d_in[4];
    const float* w3  = (const float*)d_in[5];
    const float* b3  = (const float*)d_in[6];
    const float* sw1 = (const float*)d_in[7];
    const float* sb1 = (const float*)d_in[8];
    const float* sw2 = (const float*)d_in[9];
    const float* sb2 = (const float*)d_in[10];
    const float* sw3 = (const float*)d_in[11];
    const float* sb3 = (const float*)d_in[12];
    float* out = (float*)d_out;

    const int M = in_sizes[0] / DDIM;   // 2048

    long long total = 0;
    for (int i = 7; i <= 12; i++) total += (long long)in_sizes[i];
    const unsigned int j = (unsigned int)(total / 2);

    const int nW4 = (DDIM * DDIM) / 4;
    const int nB4 = DDIM / 4;
    const int nX4 = (M * DDIM) / 4;

    // --- 1) exact global threshold via 4-pass radix select (R6-verified) ---
    rs_init<<<1, 256>>>(j);
    for (int shift = 24; shift >= 0; shift -= 8) {
        rs_hist<<<1024, 256>>>(sw1, nW4, shift);
        rs_hist<<<1024, 256>>>(sw2, nW4, shift);
        rs_hist<<<1024, 256>>>(sw3, nW4, shift);
        rs_hist<<<4,    256>>>(sb1, nB4, shift);
        rs_hist<<<4,    256>>>(sb2, nB4, shift);
        rs_hist<<<4,    256>>>(sb3, nB4, shift);
        rs_scan<<<1, 256>>>(shift);
    }

    // --- scratch symbol addresses ---
    __half *pW1, *pW2, *pW3, *pXh, *pXl, *pH1h, *pH1l, *pH2h, *pH2l;
    float *pB1, *pB2, *pB3;
    cudaGetSymbolAddress((void**)&pW1,  g_W1h);
    cudaGetSymbolAddress((void**)&pW2,  g_W2h);
    cudaGetSymbolAddress((void**)&pW3,  g_W3h);
    cudaGetSymbolAddress((void**)&pXh,  g_Xhi);
    cudaGetSymbolAddress((void**)&pXl,  g_Xlo);
    cudaGetSymbolAddress((void**)&pH1h, g_H1hi);
    cudaGetSymbolAddress((void**)&pH1l, g_H1lo);
    cudaGetSymbolAddress((void**)&pH2h, g_H2hi);
    cudaGetSymbolAddress((void**)&pH2l, g_H2lo);
    cudaGetSymbolAddress((void**)&pB1,  g_B1);
    cudaGetSymbolAddress((void**)&pB2,  g_B2);
    cudaGetSymbolAddress((void**)&pB3,  g_B3);

    // --- 2) masked weights -> fp16 ; masked biases fp32 ; split x ---
    mask_half<<<1024, 256>>>(w1, sw1, pW1, nW4);
    mask_half<<<1024, 256>>>(w2, sw2, pW2, nW4);
    mask_half<<<1024, 256>>>(w3, sw3, pW3, nW4);
    mask_mul<<<4, 256>>>(b1, sb1, pB1, nB4);
    mask_mul<<<4, 256>>>(b2, sb2, pB2, nB4);
    mask_mul<<<4, 256>>>(b3, sb3, pB3, nB4);
    split_plain_h<<<1024, 256>>>(x, pXh, pXl, nX4);

    // --- 3) three dependent fp16 2-pass HMMA GEMMs ---
    cudaFuncSetAttribute(gemm_hmma<1, 1>,
                         cudaFuncAttributeMaxDynamicSharedMemorySize, GSMEM);
    cudaFuncSetAttribute(gemm_hmma<0, 0>,
                         cudaFuncAttributeMaxDynamicSharedMemorySize, GSMEM);

    dim3 grid(DDIM / BN, M / BM);       // (32, 16)
    gemm_hmma<1, 1><<<grid, 256, GSMEM>>>(pXh,  pXl,  pW1, pB1,
                                          nullptr, pH1h, pH1l);
    gemm_hmma<1, 1><<<grid, 256, GSMEM>>>(pH1h, pH1l, pW2, pB2,
                                          nullptr, pH2h, pH2l);
    gemm_hmma<0, 0><<<grid, 256, GSMEM>>>(pH2h, pH2l, pW3, pB3,
                                          out, nullptr, nullptr);

    (void)n_in; (void)out_size;
}

// round 9
// speedup vs baseline: 2.9409x; 1.5720x over previous
#include <cuda_runtime.h>
#include <cuda_bf16.h>
#include <cuda_fp16.h>
#include <cstdint>
#include <cstddef>

#define DDIM 4096
#define BATCH 2048

// ---------------------------------------------------------------------------
// Device-global scratch
// ---------------------------------------------------------------------------
__device__ unsigned int g_hist[256];
__device__ unsigned int g_prefix;
__device__ unsigned int g_krem;
__device__ float        g_thr;

__device__ __align__(128) __half g_W1h[(size_t)DDIM * DDIM];
__device__ __align__(128) __half g_W2h[(size_t)DDIM * DDIM];
__device__ __align__(128) __half g_W3h[(size_t)DDIM * DDIM];
__device__ __align__(128) __half g_Xhi[(size_t)BATCH * DDIM];
__device__ __align__(128) __half g_Xlo[(size_t)BATCH * DDIM];
__device__ __align__(128) __half g_H1hi[(size_t)BATCH * DDIM];
__device__ __align__(128) __half g_H1lo[(size_t)BATCH * DDIM];
__device__ __align__(128) __half g_H2hi[(size_t)BATCH * DDIM];
__device__ __align__(128) __half g_H2lo[(size_t)BATCH * DDIM];
__device__ float g_B1[DDIM];
__device__ float g_B2[DDIM];
__device__ float g_B3[DDIM];

// ---------------------------------------------------------------------------
// Radix select: exact j-th smallest of all score values.
// key = (u & 0x80000000) ? ~u : (u | 0x80000000)   (ascending float order)
// Pass 1 (shift=24): heavy bin concentration -> warp-aggregated atomics.
// Passes 2-4: match rate is tiny (<=1/256 of elements) -> plain fast path.
// ---------------------------------------------------------------------------
__global__ void rs_init(unsigned int k)
{
    int t = threadIdx.x;
    if (t < 256) g_hist[t] = 0u;
    if (t == 0) { g_prefix = 0u; g_krem = k; }
}

// pass 1: histogram of key>>24 with warp aggregation (verified R6 path)
__global__ void rs_hist_p1(const float* __restrict__ p, int n4)
{
    __shared__ unsigned int sh[256];
    for (int i = threadIdx.x; i < 256; i += blockDim.x) sh[i] = 0u;
    __syncthreads();
    const float4* __restrict__ p4 = (const float4*)p;
    int i = blockIdx.x * blockDim.x + threadIdx.x;
    const int stride = gridDim.x * blockDim.x;
    for (; i < n4; i += stride) {
        float4 v = p4[i];
        float arr[4] = {v.x, v.y, v.z, v.w};
        #pragma unroll
        for (int c = 0; c < 4; c++) {
            unsigned int u   = __float_as_uint(arr[c]);
            unsigned int key = (u & 0x80000000u) ? ~u : (u | 0x80000000u);
            unsigned int bin = key >> 24;
            unsigned int amask = __activemask();
            unsigned int peers = __match_any_sync(amask, bin);
            if ((int)(threadIdx.x & 31u) == __ffs(peers) - 1)
                atomicAdd(&sh[bin], (unsigned int)__popc(peers));
        }
    }
    __syncthreads();
    for (int i2 = threadIdx.x; i2 < 256; i2 += blockDim.x) {
        unsigned int cv = sh[i2];
        if (cv) atomicAdd(&g_hist[i2], cv);
    }
}

// passes 2-4: prefix match is rare -> no aggregation needed
__global__ void rs_hist_rest(const float* __restrict__ p, int n4, int shift)
{
    __shared__ unsigned int sh[256];
    for (int i = threadIdx.x; i < 256; i += blockDim.x) sh[i] = 0u;
    __syncthreads();
    const unsigned int pref = g_prefix;
    const float4* __restrict__ p4 = (const float4*)p;
    int i = blockIdx.x * blockDim.x + threadIdx.x;
    const int stride = gridDim.x * blockDim.x;
    for (; i < n4; i += stride) {
        float4 v = p4[i];
        float arr[4] = {v.x, v.y, v.z, v.w};
        #pragma unroll
        for (int c = 0; c < 4; c++) {
            unsigned int u   = __float_as_uint(arr[c]);
            unsigned int key = (u & 0x80000000u) ? ~u : (u | 0x80000000u);
            if (((key ^ pref) >> (shift + 8)) == 0u)
                atomicAdd(&sh[(key >> shift) & 0xffu], 1u);
        }
    }
    __syncthreads();
    for (int i2 = threadIdx.x; i2 < 256; i2 += blockDim.x) {
        unsigned int cv = sh[i2];
        if (cv) atomicAdd(&g_hist[i2], cv);
    }
}

__global__ void rs_scan(int shift)
{
    __shared__ unsigned int s[256];
    const int t = threadIdx.x;
    unsigned int c = g_hist[t];
    g_hist[t] = 0u;
    s[t] = c;
    __syncthreads();
    #pragma unroll
    for (int off = 1; off < 256; off <<= 1) {
        unsigned int add = (t >= off) ? s[t - off] : 0u;
        __syncthreads();
        s[t] += add;
        __syncthreads();
    }
    const unsigned int inc = s[t];
    const unsigned int exc = inc - c;
    const unsigned int k   = g_krem;
    if (k >= exc && k < inc) {
        unsigned int newpref = g_prefix | ((unsigned int)t << shift);
        g_prefix = newpref;
        g_krem   = k - exc;
        if (shift == 0) {
            unsigned int u = (newpref & 0x80000000u) ? (newpref ^ 0x80000000u)
                                                     : ~newpref;
            g_thr = __uint_as_float(u);
        }
    }
}

// ---------------------------------------------------------------------------
// fp16 split helpers + mask kernels
// ---------------------------------------------------------------------------
__device__ __forceinline__ void split2h(float f0, float f1,
                                        unsigned int& h, unsigned int& l)
{
    __half h0 = __float2half_rn(f0);
    __half h1 = __float2half_rn(f1);
    __half l0 = __float2half_rn(f0 - __half2float(h0));
    __half l1 = __float2half_rn(f1 - __half2float(h1));
    h = (unsigned int)__half_as_ushort(h0) |
        ((unsigned int)__half_as_ushort(h1) << 16);
    l = (unsigned int)__half_as_ushort(l0) |
        ((unsigned int)__half_as_ushort(l1) << 16);
}

__global__ void mask_half(const float* __restrict__ w,
                          const float* __restrict__ s,
                          __half* __restrict__ out, int n4)
{
    const float thr = g_thr;
    const float4* __restrict__ w4 = (const float4*)w;
    const float4* __restrict__ s4 = (const float4*)s;
    uint2* __restrict__ o2 = (uint2*)out;
    int i = blockIdx.x * blockDim.x + threadIdx.x;
    const int stride = gridDim.x * blockDim.x;
    for (; i < n4; i += stride) {
        float4 wv = w4[i];
        float4 sv = s4[i];
        float f0 = (sv.x >= thr) ? wv.x : 0.0f;
        float f1 = (sv.y >= thr) ? wv.y : 0.0f;
        float f2 = (sv.z >= thr) ? wv.z : 0.0f;
        float f3 = (sv.w >= thr) ? wv.w : 0.0f;
        uint2 o;
        o.x = (unsigned int)__half_as_ushort(__float2half_rn(f0)) |
              ((unsigned int)__half_as_ushort(__float2half_rn(f1)) << 16);
        o.y = (unsigned int)__half_as_ushort(__float2half_rn(f2)) |
              ((unsigned int)__half_as_ushort(__float2half_rn(f3)) << 16);
        o2[i] = o;
    }
}

__global__ void split_plain_h(const float* __restrict__ in,
                              __half* __restrict__ hi,
                              __half* __restrict__ lo, int n4)
{
    const float4* __restrict__ p4 = (const float4*)in;
    uint2* __restrict__ h2 = (uint2*)hi;
    uint2* __restrict__ l2 = (uint2*)lo;
    int i = blockIdx.x * blockDim.x + threadIdx.x;
    const int stride = gridDim.x * blockDim.x;
    for (; i < n4; i += stride) {
        float4 v = p4[i];
        uint2 hu, lu;
        split2h(v.x, v.y, hu.x, lu.x);
        split2h(v.z, v.w, hu.y, lu.y);
        h2[i] = hu;
        l2[i] = lu;
    }
}

__global__ void mask_mul(const float* __restrict__ w,
                         const float* __restrict__ s,
                         float* __restrict__ out, int n4)
{
    const float thr = g_thr;
    const float4* __restrict__ w4 = (const float4*)w;
    const float4* __restrict__ s4 = (const float4*)s;
    float4* __restrict__ o4 = (float4*)out;
    int i = blockIdx.x * blockDim.x + threadIdx.x;
    const int stride = gridDim.x * blockDim.x;
    for (; i < n4; i += stride) {
        float4 wv = w4[i];
        float4 sv = s4[i];
        float4 r;
        r.x = (sv.x >= thr) ? wv.x : 0.0f;
        r.y = (sv.y >= thr) ? wv.y : 0.0f;
        r.z = (sv.z >= thr) ? wv.z : 0.0f;
        r.w = (sv.w >= thr) ? wv.w : 0.0f;
        o4[i] = r;
    }
}

// ---------------------------------------------------------------------------
// cp.async + ldmatrix + mma.sync (fp16)
// ---------------------------------------------------------------------------
__device__ __forceinline__ uint32_t smem_u32(const void* p)
{
    uint32_t a;
    asm("{ .reg .u64 t; cvta.to.shared.u64 t, %1; cvt.u32.u64 %0, t; }"
        : "=r"(a) : "l"(p));
    return a;
}

__device__ __forceinline__ void cpasync16(uint32_t dst, const void* src)
{
    asm volatile("cp.async.cg.shared.global [%0], [%1], 16;"
                 :: "r"(dst), "l"(src) : "memory");
}
#define CP_COMMIT() asm volatile("cp.async.commit_group;" ::: "memory")
#define CP_WAIT_1() asm volatile("cp.async.wait_group 1;" ::: "memory")

__device__ __forceinline__ void ldsm4(uint32_t& r0, uint32_t& r1,
                                      uint32_t& r2, uint32_t& r3, uint32_t a)
{
    asm volatile("ldmatrix.sync.aligned.m8n8.x4.shared.b16 {%0,%1,%2,%3}, [%4];"
                 : "=r"(r0), "=r"(r1), "=r"(r2), "=r"(r3) : "r"(a));
}

__device__ __forceinline__ void mma16816h(float* c,
                                          uint32_t a0, uint32_t a1,
                                          uint32_t a2, uint32_t a3,
                                          uint32_t b0, uint32_t b1)
{
    asm volatile(
        "mma.sync.aligned.m16n8k16.row.col.f32.f16.f16.f32 "
        "{%0,%1,%2,%3}, {%4,%5,%6,%7}, {%8,%9}, {%0,%1,%2,%3};"
        : "+f"(c[0]), "+f"(c[1]), "+f"(c[2]), "+f"(c[3])
        : "r"(a0), "r"(a1), "r"(a2), "r"(a3), "r"(b0), "r"(b1));
}

// ---------------------------------------------------------------------------
// fp16 2-pass HMMA GEMM: C = Ahi@B^T + Alo@B^T + bias (opt ReLU)
// 3-stage cp.async; 8 warps 2(M)x4(N); warp tile 64x32; BK=32.
// __launch_bounds__(256, 2): cap 128 regs -> 2 CTAs/SM (smem 2x73.7KB fits).
// ---------------------------------------------------------------------------
#define BM 128
#define BN 128
#define BK 32
#define GSTAGES 3
#define STG_B (3 * BM * BK * 2)        /* 24576 bytes per stage */
#define GSMEM  (GSTAGES * STG_B)       /* 73728 */

template<int RELU, int OUT_HALF>
__global__ void __launch_bounds__(256, 2) gemm_hmma(
    const __half* __restrict__ Ah, const __half* __restrict__ Al,
    const __half* __restrict__ B,
    const float* __restrict__ bias,
    float* __restrict__ outf,
    __half* __restrict__ outhi,
    __half* __restrict__ outlo)
{
    extern __shared__ __align__(128) char smem[];
    const uint32_t sbase = smem_u32(smem);
    const int tid  = threadIdx.x;
    const int lane = tid & 31;
    const int wid  = tid >> 5;
    const int wm   = wid >> 2;          // 0..1
    const int wn   = wid & 3;           // 0..3
    const int bx   = blockIdx.x;        // N tile
    const int by   = blockIdx.y;        // M tile
    const int K    = DDIM;

    const int lrow = tid >> 2;          // 0..63
    const int lch  = tid & 3;           // 16B chunk within 64B row
    const uint32_t d0 = (uint32_t)lrow * 64 + (uint32_t)((lch ^ (lrow & 3)) << 4);

    const int rowA = by * BM;
    const int rowB = bx * BN;
    const __half* sAh0 = Ah + (size_t)(rowA + lrow) * K + lch * 8;
    const __half* sAh1 = Ah + (size_t)(rowA + lrow + 64) * K + lch * 8;
    const __half* sAl0 = Al + (size_t)(rowA + lrow) * K + lch * 8;
    const __half* sAl1 = Al + (size_t)(rowA + lrow + 64) * K + lch * 8;
    const __half* sB0  = B  + (size_t)(rowB + lrow) * K + lch * 8;
    const __half* sB1  = B  + (size_t)(rowB + lrow + 64) * K + lch * 8;

    #define LOAD_STAGE(stg, kt) do {                                          \
        const uint32_t s0 = sbase + (uint32_t)(stg) * STG_B + d0;             \
        const size_t ko = (size_t)(kt) * BK;                                  \
        cpasync16(s0,          sAh0 + ko);                                    \
        cpasync16(s0 + 4096,   sAh1 + ko);                                    \
        cpasync16(s0 + 8192,   sAl0 + ko);                                    \
        cpasync16(s0 + 12288,  sAl1 + ko);                                    \
        cpasync16(s0 + 16384,  sB0  + ko);                                    \
        cpasync16(s0 + 20480,  sB1  + ko);                                    \
    } while (0)

    float c[4][4][4];
    #pragma unroll
    for (int i = 0; i < 4; i++)
        #pragma unroll
        for (int j = 0; j < 4; j++)
            #pragma unroll
            for (int q = 0; q < 4; q++) c[i][j][q] = 0.0f;

    const int NT = K / BK;              // 128

    LOAD_STAGE(0, 0); CP_COMMIT();
    LOAD_STAGE(1, 1); CP_COMMIT();

    const int fr = lane & 15;
    const int fh = lane >> 4;

    for (int t = 0; t < NT; t++) {
        CP_WAIT_1();
        __syncthreads();

        const int lt = t + GSTAGES - 1;
        if (lt < NT) LOAD_STAGE(lt % GSTAGES, lt);
        CP_COMMIT();

        const uint32_t sb = sbase + (uint32_t)(t % GSTAGES) * STG_B;

        #pragma unroll
        for (int kk = 0; kk < 2; kk++) {
            const int chb = kk * 2 + fh;

            uint32_t aoff[4], boff[2];
            #pragma unroll
            for (int mi = 0; mi < 4; mi++) {
                const int row = wm * 64 + mi * 16 + fr;
                aoff[mi] = (uint32_t)row * 64 + (uint32_t)((chb ^ (row & 3)) << 4);
            }
            #pragma unroll
            for (int nj = 0; nj < 2; nj++) {
                const int row = wn * 32 + nj * 16 + fr;
                boff[nj] = (uint32_t)row * 64 + (uint32_t)((chb ^ (row & 3)) << 4);
            }

            uint32_t b[2][4];
            #pragma unroll
            for (int nj = 0; nj < 2; nj++)
                ldsm4(b[nj][0], b[nj][1], b[nj][2], b[nj][3],
                      sb + 16384u + boff[nj]);

            #pragma unroll
            for (int mi = 0; mi < 4; mi++) {
                uint32_t a0, a1, a2, a3;
                ldsm4(a0, a1, a2, a3, sb + aoff[mi]);
                mma16816h(c[mi][0], a0, a1, a2, a3, b[0][0], b[0][2]);
                mma16816h(c[mi][1], a0, a1, a2, a3, b[0][1], b[0][3]);
                mma16816h(c[mi][2], a0, a1, a2, a3, b[1][0], b[1][2]);
                mma16816h(c[mi][3], a0, a1, a2, a3, b[1][1], b[1][3]);
            }
            #pragma unroll
            for (int mi = 0; mi < 4; mi++) {
                uint32_t a0, a1, a2, a3;
                ldsm4(a0, a1, a2, a3, sb + 8192u + aoff[mi]);
                mma16816h(c[mi][0], a0, a1, a2, a3, b[0][0], b[0][2]);
                mma16816h(c[mi][1], a0, a1, a2, a3, b[0][1], b[0][3]);
                mma16816h(c[mi][2], a0, a1, a2, a3, b[1][0], b[1][2]);
                mma16816h(c[mi][3], a0, a1, a2, a3, b[1][1], b[1][3]);
            }
        }
    }

    const int q   = lane >> 2;
    const int rp  = lane & 3;
    const int m0g = by * BM + wm * 64;
    const int n0g = bx * BN + wn * 32;

    #pragma unroll
    for (int mi = 0; mi < 4; mi++) {
        #pragma unroll
        for (int ni = 0; ni < 4; ni++) {
            const int col = n0g + ni * 8 + rp * 2;
            const float bv0 = __ldg(bias + col);
            const float bv1 = __ldg(bias + col + 1);
            float v0 = c[mi][ni][0] + bv0;
            float v1 = c[mi][ni][1] + bv1;
            float v2 = c[mi][ni][2] + bv0;
            float v3 = c[mi][ni][3] + bv1;
            if (RELU) {
                v0 = fmaxf(v0, 0.0f); v1 = fmaxf(v1, 0.0f);
                v2 = fmaxf(v2, 0.0f); v3 = fmaxf(v3, 0.0f);
            }
            const int r0 = m0g + mi * 16 + q;
            const int r1 = r0 + 8;
            if (OUT_HALF) {
                unsigned int h, l;
                split2h(v0, v1, h, l);
                *(unsigned int*)(outhi + (size_t)r0 * DDIM + col) = h;
                *(unsigned int*)(outlo + (size_t)r0 * DDIM + col) = l;
                split2h(v2, v3, h, l);
                *(unsigned int*)(outhi + (size_t)r1 * DDIM + col) = h;
                *(unsigned int*)(outlo + (size_t)r1 * DDIM + col) = l;
            } else {
                *(float2*)(outf + (size_t)r0 * DDIM + col) = make_float2(v0, v1);
                *(float2*)(outf + (size_t)r1 * DDIM + col) = make_float2(v2, v3);
            }
        }
    }
    #undef LOAD_STAGE
}

// ---------------------------------------------------------------------------
// kernel_launch
// ---------------------------------------------------------------------------
extern "C" void kernel_launch(void* const* d_in, const int* in_sizes, int n_in,
                              void* d_out, int out_size)
{
    const float* x   = (const float*)d_in[0];
    const float* w1  = (const float*)d_in[1];
    const float* b1  = (const float*)d_in[2];
    const float* w2  = (const float*)d_in[3];
    const float* b2  = (const float*)d_in[4];
    const float* w3  = (const float*)d_in[5];
    const float* b3  = (const float*)d_in[6];
    const float* sw1 = (const float*)d_in[7];
    const float* sb1 = (const float*)d_in[8];
    const float* sw2 = (const float*)d_in[9];
    const float* sb2 = (const float*)d_in[10];
    const float* sw3 = (const float*)d_in[11];
    const float* sb3 = (const float*)d_in[12];
    float* out = (float*)d_out;

    const int M = in_sizes[0] / DDIM;   // 2048

    long long total = 0;
    for (int i = 7; i <= 12; i++) total += (long long)in_sizes[i];
    const unsigned int j = (unsigned int)(total / 2);

    const int nW4 = (DDIM * DDIM) / 4;
    const int nB4 = DDIM / 4;
    const int nX4 = (M * DDIM) / 4;

    // --- 1) exact global threshold via 4-pass radix select ---
    rs_init<<<1, 256>>>(j);
    // pass 1 (shift=24): aggregated histogram
    rs_hist_p1<<<1024, 256>>>(sw1, nW4);
    rs_hist_p1<<<1024, 256>>>(sw2, nW4);
    rs_hist_p1<<<1024, 256>>>(sw3, nW4);
    rs_hist_p1<<<4,    256>>>(sb1, nB4);
    rs_hist_p1<<<4,    256>>>(sb2, nB4);
    rs_hist_p1<<<4,    256>>>(sb3, nB4);
    rs_scan<<<1, 256>>>(24);
    // passes 2-4: rare-match fast path
    for (int shift = 16; shift >= 0; shift -= 8) {
        rs_hist_rest<<<1024, 256>>>(sw1, nW4, shift);
        rs_hist_rest<<<1024, 256>>>(sw2, nW4, shift);
        rs_hist_rest<<<1024, 256>>>(sw3, nW4, shift);
        rs_hist_rest<<<4,    256>>>(sb1, nB4, shift);
        rs_hist_rest<<<4,    256>>>(sb2, nB4, shift);
        rs_hist_rest<<<4,    256>>>(sb3, nB4, shift);
        rs_scan<<<1, 256>>>(shift);
    }

    // --- scratch symbol addresses ---
    __half *pW1, *pW2, *pW3, *pXh, *pXl, *pH1h, *pH1l, *pH2h, *pH2l;
    float *pB1, *pB2, *pB3;
    cudaGetSymbolAddress((void**)&pW1,  g_W1h);
    cudaGetSymbolAddress((void**)&pW2,  g_W2h);
    cudaGetSymbolAddress((void**)&pW3,  g_W3h);
    cudaGetSymbolAddress((void**)&pXh,  g_Xhi);
    cudaGetSymbolAddress((void**)&pXl,  g_Xlo);
    cudaGetSymbolAddress((void**)&pH1h, g_H1hi);
    cudaGetSymbolAddress((void**)&pH1l, g_H1lo);
    cudaGetSymbolAddress((void**)&pH2h, g_H2hi);
    cudaGetSymbolAddress((void**)&pH2l, g_H2lo);
    cudaGetSymbolAddress((void**)&pB1,  g_B1);
    cudaGetSymbolAddress((void**)&pB2,  g_B2);
    cudaGetSymbolAddress((void**)&pB3,  g_B3);

    // --- 2) masked weights -> fp16 ; masked biases fp32 ; split x ---
    mask_half<<<1024, 256>>>(w1, sw1, pW1, nW4);
    mask_half<<<1024, 256>>>(w2, sw2, pW2, nW4);
    mask_half<<<1024, 256>>>(w3, sw3, pW3, nW4);
    mask_mul<<<4, 256>>>(b1, sb1, pB1, nB4);
    mask_mul<<<4, 256>>>(b2, sb2, pB2, nB4);
    mask_mul<<<4, 256>>>(b3, sb3, pB3, nB4);
    split_plain_h<<<1024, 256>>>(x, pXh, pXl, nX4);

    // --- 3) three dependent fp16 2-pass HMMA GEMMs ---
    cudaFuncSetAttribute(gemm_hmma<1, 1>,
                         cudaFuncAttributeMaxDynamicSharedMemorySize, GSMEM);
    cudaFuncSetAttribute(gemm_hmma<0, 0>,
                         cudaFuncAttributeMaxDynamicSharedMemorySize, GSMEM);

    dim3 grid(DDIM / BN, M / BM);       // (32, 16)
    gemm_hmma<1, 1><<<grid, 256, GSMEM>>>(pXh,  pXl,  pW1, pB1,
                                          nullptr, pH1h, pH1l);
    gemm_hmma<1, 1><<<grid, 256, GSMEM>>>(pH1h, pH1l, pW2, pB2,
                                          nullptr, pH2h, pH2l);
    gemm_hmma<0, 0><<<grid, 256, GSMEM>>>(pH2h, pH2l, pW3, pB3,
                                          out, nullptr, nullptr);

    (void)n_in; (void)out_size;
}

// round 10
// speedup vs baseline: 3.1126x; 1.0584x over previous
#include <cuda_runtime.h>
#include <cuda_bf16.h>
#include <cuda_fp16.h>
#include <cstdint>
#include <cstddef>

#define DDIM 4096
#define BATCH 2048
#define CAND_CAP (1u << 22)

// ---------------------------------------------------------------------------
// Device-global scratch
// ---------------------------------------------------------------------------
__device__ unsigned int g_hist[256];
__device__ unsigned int g_prefix;
__device__ unsigned int g_krem;
__device__ float        g_thr;
__device__ unsigned int g_cand[CAND_CAP];
__device__ unsigned int g_cand_cnt;

__device__ __align__(128) __half g_W1h[(size_t)DDIM * DDIM];
__device__ __align__(128) __half g_W2h[(size_t)DDIM * DDIM];
__device__ __align__(128) __half g_W3h[(size_t)DDIM * DDIM];
__device__ __align__(128) __half g_Xhi[(size_t)BATCH * DDIM];
__device__ __align__(128) __half g_Xlo[(size_t)BATCH * DDIM];
__device__ __align__(128) __half g_H1hi[(size_t)BATCH * DDIM];
__device__ __align__(128) __half g_H1lo[(size_t)BATCH * DDIM];
__device__ __align__(128) __half g_H2hi[(size_t)BATCH * DDIM];
__device__ __align__(128) __half g_H2lo[(size_t)BATCH * DDIM];
__device__ float g_B1[DDIM];
__device__ float g_B2[DDIM];
__device__ float g_B3[DDIM];

// ---------------------------------------------------------------------------
// Radix select: exact j-th smallest of all score values.
// key = (u & 0x80000000) ? ~u : (u | 0x80000000)   (ascending float order)
// Pass 1 (8-bit, aggregated) + pass 2 (8-bit, rare-match) locate a 16-bit
// prefix; compaction gathers its ~50K members; a single block finishes.
// ---------------------------------------------------------------------------
__device__ __forceinline__ unsigned int f2key(float f)
{
    unsigned int u = __float_as_uint(f);
    return (u & 0x80000000u) ? ~u : (u | 0x80000000u);
}

__global__ void rs_init(unsigned int k)
{
    int t = threadIdx.x;
    if (t < 256) g_hist[t] = 0u;
    if (t == 0) { g_prefix = 0u; g_krem = k; g_cand_cnt = 0u; }
}

// pass 1: histogram of key>>24 with warp aggregation; 2-way load ILP
__global__ void rs_hist_p1(const float* __restrict__ p, int n4)
{
    __shared__ unsigned int sh[256];
    for (int i = threadIdx.x; i < 256; i += blockDim.x) sh[i] = 0u;
    __syncthreads();
    const float4* __restrict__ p4 = (const float4*)p;
    const int stride = gridDim.x * blockDim.x;
    int i = blockIdx.x * blockDim.x + threadIdx.x;
    const int lane = threadIdx.x & 31;
    for (; i < n4; i += 2 * stride) {
        float4 v0 = p4[i];
        bool has2 = (i + stride) < n4;
        float4 v1 = has2 ? p4[i + stride] : make_float4(0, 0, 0, 0);
        float arr[8] = {v0.x, v0.y, v0.z, v0.w, v1.x, v1.y, v1.z, v1.w};
        const int cnt = has2 ? 8 : 4;
        for (int c = 0; c < cnt; c++) {
            unsigned int bin = f2key(arr[c]) >> 24;
            unsigned int amask = __activemask();
            unsigned int peers = __match_any_sync(amask, bin);
            if (lane == __ffs(peers) - 1)
                atomicAdd(&sh[bin], (unsigned int)__popc(peers));
        }
    }
    __syncthreads();
    for (int i2 = threadIdx.x; i2 < 256; i2 += blockDim.x) {
        unsigned int cv = sh[i2];
        if (cv) atomicAdd(&g_hist[i2], cv);
    }
}

// pass 2 (shift=16): prefix match is rare -> plain fast path
__global__ void rs_hist_p2(const float* __restrict__ p, int n4)
{
    __shared__ unsigned int sh[256];
    for (int i = threadIdx.x; i < 256; i += blockDim.x) sh[i] = 0u;
    __syncthreads();
    const unsigned int pref = g_prefix;
    const float4* __restrict__ p4 = (const float4*)p;
    int i = blockIdx.x * blockDim.x + threadIdx.x;
    const int stride = gridDim.x * blockDim.x;
    for (; i < n4; i += stride) {
        float4 v = p4[i];
        float arr[4] = {v.x, v.y, v.z, v.w};
        #pragma unroll
        for (int c = 0; c < 4; c++) {
            unsigned int key = f2key(arr[c]);
            if (((key ^ pref) >> 24) == 0u)
                atomicAdd(&sh[(key >> 16) & 0xffu], 1u);
        }
    }
    __syncthreads();
    for (int i2 = threadIdx.x; i2 < 256; i2 += blockDim.x) {
        unsigned int cv = sh[i2];
        if (cv) atomicAdd(&g_hist[i2], cv);
    }
}

__global__ void rs_scan(int shift)
{
    __shared__ unsigned int s[256];
    const int t = threadIdx.x;
    unsigned int c = g_hist[t];
    g_hist[t] = 0u;
    s[t] = c;
    __syncthreads();
    #pragma unroll
    for (int off = 1; off < 256; off <<= 1) {
        unsigned int add = (t >= off) ? s[t - off] : 0u;
        __syncthreads();
        s[t] += add;
        __syncthreads();
    }
    const unsigned int inc = s[t];
    const unsigned int exc = inc - c;
    const unsigned int k   = g_krem;
    if (k >= exc && k < inc) {
        g_prefix = g_prefix | ((unsigned int)t << shift);
        g_krem   = k - exc;
    }
}

// gather keys whose top 16 bits match g_prefix>>16 (R7-verified pattern)
__global__ void rs_compact(const float* __restrict__ p, int n4)
{
    const unsigned int pref16 = g_prefix >> 16;
    const float4* __restrict__ p4 = (const float4*)p;
    int i = blockIdx.x * blockDim.x + threadIdx.x;
    const int stride = gridDim.x * blockDim.x;
    const int lane = threadIdx.x & 31;
    for (; i < n4; i += stride) {
        float4 v = p4[i];
        float arr[4] = {v.x, v.y, v.z, v.w};
        #pragma unroll
        for (int c = 0; c < 4; c++) {
            unsigned int key = f2key(arr[c]);
            bool m = (key >> 16) == pref16;
            unsigned int amask = __activemask();
            unsigned int bal = __ballot_sync(amask, m);
            if (m) {
                int leader = __ffs(bal) - 1;
                unsigned int base = 0;
                if (lane == leader)
                    base = atomicAdd(&g_cand_cnt, (unsigned int)__popc(bal));
                base = __shfl_sync(bal, base, leader);
                unsigned int idx = base + __popc(bal & ((1u << lane) - 1u));
                if (idx < CAND_CAP) g_cand[idx] = key;
            }
        }
    }
}

// single block: finish low 16 bits over the small candidate set (R7-verified)
__global__ void rs_final()
{
    __shared__ unsigned int sh[256];
    __shared__ unsigned int s_b2, s_k2;
    const int tid = threadIdx.x;   // 1024
    unsigned int n = g_cand_cnt;
    if (n > CAND_CAP) n = CAND_CAP;
    const unsigned int k = g_krem;

    if (tid < 256) sh[tid] = 0u;
    __syncthreads();
    for (unsigned int i = tid; i < n; i += 1024)
        atomicAdd(&sh[(g_cand[i] >> 8) & 0xffu], 1u);
    __syncthreads();
    if (tid == 0) {
        unsigned int run = 0;
        for (int b = 0; b < 256; b++) {
            unsigned int c = sh[b];
            if (k < run + c) { s_b2 = (unsigned int)b; s_k2 = k - run; break; }
            run += c;
        }
    }
    __syncthreads();
    const unsigned int b2 = s_b2, k2 = s_k2;
    if (tid < 256) sh[tid] = 0u;
    __syncthreads();
    for (unsigned int i = tid; i < n; i += 1024) {
        unsigned int key = g_cand[i];
        if (((key >> 8) & 0xffu) == b2) atomicAdd(&sh[key & 0xffu], 1u);
    }
    __syncthreads();
    if (tid == 0) {
        unsigned int run = 0;
        for (int b = 0; b < 256; b++) {
            unsigned int c = sh[b];
            if (k2 < run + c) {
                unsigned int key = g_prefix | (b2 << 8) | (unsigned int)b;
                unsigned int u = (key & 0x80000000u) ? (key ^ 0x80000000u) : ~key;
                g_thr = __uint_as_float(u);
                break;
            }
            run += c;
        }
    }
}

// ---------------------------------------------------------------------------
// fp16 split helpers + mask kernels
// ---------------------------------------------------------------------------
__device__ __forceinline__ void split2h(float f0, float f1,
                                        unsigned int& h, unsigned int& l)
{
    __half h0 = __float2half_rn(f0);
    __half h1 = __float2half_rn(f1);
    __half l0 = __float2half_rn(f0 - __half2float(h0));
    __half l1 = __float2half_rn(f1 - __half2float(h1));
    h = (unsigned int)__half_as_ushort(h0) |
        ((unsigned int)__half_as_ushort(h1) << 16);
    l = (unsigned int)__half_as_ushort(l0) |
        ((unsigned int)__half_as_ushort(l1) << 16);
}

__global__ void mask_half(const float* __restrict__ w,
                          const float* __restrict__ s,
                          __half* __restrict__ out, int n4)
{
    const float thr = g_thr;
    const float4* __restrict__ w4 = (const float4*)w;
    const float4* __restrict__ s4 = (const float4*)s;
    uint2* __restrict__ o2 = (uint2*)out;
    int i = blockIdx.x * blockDim.x + threadIdx.x;
    const int stride = gridDim.x * blockDim.x;
    for (; i < n4; i += stride) {
        float4 wv = w4[i];
        float4 sv = s4[i];
        float f0 = (sv.x >= thr) ? wv.x : 0.0f;
        float f1 = (sv.y >= thr) ? wv.y : 0.0f;
        float f2 = (sv.z >= thr) ? wv.z : 0.0f;
        float f3 = (sv.w >= thr) ? wv.w : 0.0f;
        uint2 o;
        o.x = (unsigned int)__half_as_ushort(__float2half_rn(f0)) |
              ((unsigned int)__half_as_ushort(__float2half_rn(f1)) << 16);
        o.y = (unsigned int)__half_as_ushort(__float2half_rn(f2)) |
              ((unsigned int)__half_as_ushort(__float2half_rn(f3)) << 16);
        o2[i] = o;
    }
}

__global__ void split_plain_h(const float* __restrict__ in,
                              __half* __restrict__ hi,
                              __half* __restrict__ lo, int n4)
{
    const float4* __restrict__ p4 = (const float4*)in;
    uint2* __restrict__ h2 = (uint2*)hi;
    uint2* __restrict__ l2 = (uint2*)lo;
    int i = blockIdx.x * blockDim.x + threadIdx.x;
    const int stride = gridDim.x * blockDim.x;
    for (; i < n4; i += stride) {
        float4 v = p4[i];
        uint2 hu, lu;
        split2h(v.x, v.y, hu.x, lu.x);
        split2h(v.z, v.w, hu.y, lu.y);
        h2[i] = hu;
        l2[i] = lu;
    }
}

__global__ void mask_mul(const float* __restrict__ w,
                         const float* __restrict__ s,
                         float* __restrict__ out, int n4)
{
    const float thr = g_thr;
    const float4* __restrict__ w4 = (const float4*)w;
    const float4* __restrict__ s4 = (const float4*)s;
    float4* __restrict__ o4 = (float4*)out;
    int i = blockIdx.x * blockDim.x + threadIdx.x;
    const int stride = gridDim.x * blockDim.x;
    for (; i < n4; i += stride) {
        float4 wv = w4[i];
        float4 sv = s4[i];
        float4 r;
        r.x = (sv.x >= thr) ? wv.x : 0.0f;
        r.y = (sv.y >= thr) ? wv.y : 0.0f;
        r.z = (sv.z >= thr) ? wv.z : 0.0f;
        r.w = (sv.w >= thr) ? wv.w : 0.0f;
        o4[i] = r;
    }
}

// ---------------------------------------------------------------------------
// cp.async + ldmatrix + mma.sync (fp16)
// ---------------------------------------------------------------------------
__device__ __forceinline__ uint32_t smem_u32(const void* p)
{
    uint32_t a;
    asm("{ .reg .u64 t; cvta.to.shared.u64 t, %1; cvt.u32.u64 %0, t; }"
        : "=r"(a) : "l"(p));
    return a;
}

__device__ __forceinline__ void cpasync16(uint32_t dst, const void* src)
{
    asm volatile("cp.async.cg.shared.global [%0], [%1], 16;"
                 :: "r"(dst), "l"(src) : "memory");
}
#define CP_COMMIT() asm volatile("cp.async.commit_group;" ::: "memory")
#define CP_WAIT_2() asm volatile("cp.async.wait_group 2;" ::: "memory")

__device__ __forceinline__ void ldsm4(uint32_t& r0, uint32_t& r1,
                                      uint32_t& r2, uint32_t& r3, uint32_t a)
{
    asm volatile("ldmatrix.sync.aligned.m8n8.x4.shared.b16 {%0,%1,%2,%3}, [%4];"
                 : "=r"(r0), "=r"(r1), "=r"(r2), "=r"(r3) : "r"(a));
}

__device__ __forceinline__ void mma16816h(float* c,
                                          uint32_t a0, uint32_t a1,
                                          uint32_t a2, uint32_t a3,
                                          uint32_t b0, uint32_t b1)
{
    asm volatile(
        "mma.sync.aligned.m16n8k16.row.col.f32.f16.f16.f32 "
        "{%0,%1,%2,%3}, {%4,%5,%6,%7}, {%8,%9}, {%0,%1,%2,%3};"
        : "+f"(c[0]), "+f"(c[1]), "+f"(c[2]), "+f"(c[3])
        : "r"(a0), "r"(a1), "r"(a2), "r"(a3), "r"(b0), "r"(b1));
}

// ---------------------------------------------------------------------------
// fp16 2-pass HMMA GEMM: C = Ahi@B^T + Alo@B^T + bias (opt ReLU)
// 4-stage cp.async (prefetch depth 2); 8 warps 2(M)x4(N); warp tile 64x32.
// __launch_bounds__(256, 2): 2 CTAs/SM (2 x 96KB smem fits 228KB carveout).
// ---------------------------------------------------------------------------
#define BM 128
#define BN 128
#define BK 32
#define GSTAGES 4
#define STG_B (3 * BM * BK * 2)        /* 24576 bytes per stage */
#define GSMEM  (GSTAGES * STG_B)       /* 98304 */

template<int RELU, int OUT_HALF>
__global__ void __launch_bounds__(256, 2) gemm_hmma(
    const __half* __restrict__ Ah, const __half* __restrict__ Al,
    const __half* __restrict__ B,
    const float* __restrict__ bias,
    float* __restrict__ outf,
    __half* __restrict__ outhi,
    __half* __restrict__ outlo)
{
    extern __shared__ __align__(128) char smem[];
    const uint32_t sbase = smem_u32(smem);
    const int tid  = threadIdx.x;
    const int lane = tid & 31;
    const int wid  = tid >> 5;
    const int wm   = wid >> 2;          // 0..1
    const int wn   = wid & 3;           // 0..3
    const int bx   = blockIdx.x;        // N tile
    const int by   = blockIdx.y;        // M tile
    const int K    = DDIM;

    const int lrow = tid >> 2;          // 0..63
    const int lch  = tid & 3;           // 16B chunk within 64B row
    const uint32_t d0 = (uint32_t)lrow * 64 + (uint32_t)((lch ^ (lrow & 3)) << 4);

    const int rowA = by * BM;
    const int rowB = bx * BN;
    const __half* sAh0 = Ah + (size_t)(rowA + lrow) * K + lch * 8;
    const __half* sAh1 = Ah + (size_t)(rowA + lrow + 64) * K + lch * 8;
    const __half* sAl0 = Al + (size_t)(rowA + lrow) * K + lch * 8;
    const __half* sAl1 = Al + (size_t)(rowA + lrow + 64) * K + lch * 8;
    const __half* sB0  = B  + (size_t)(rowB + lrow) * K + lch * 8;
    const __half* sB1  = B  + (size_t)(rowB + lrow + 64) * K + lch * 8;

    #define LOAD_STAGE(stg, kt) do {                                          \
        const uint32_t s0 = sbase + (uint32_t)(stg) * STG_B + d0;             \
        const size_t ko = (size_t)(kt) * BK;                                  \
        cpasync16(s0,          sAh0 + ko);                                    \
        cpasync16(s0 + 4096,   sAh1 + ko);                                    \
        cpasync16(s0 + 8192,   sAl0 + ko);                                    \
        cpasync16(s0 + 12288,  sAl1 + ko);                                    \
        cpasync16(s0 + 16384,  sB0  + ko);                                    \
        cpasync16(s0 + 20480,  sB1  + ko);                                    \
    } while (0)

    float c[4][4][4];
    #pragma unroll
    for (int i = 0; i < 4; i++)
        #pragma unroll
        for (int j = 0; j < 4; j++)
            #pragma unroll
            for (int q = 0; q < 4; q++) c[i][j][q] = 0.0f;

    const int NT = K / BK;              // 128

    LOAD_STAGE(0, 0); CP_COMMIT();
    LOAD_STAGE(1, 1); CP_COMMIT();
    LOAD_STAGE(2, 2); CP_COMMIT();

    const int fr = lane & 15;
    const int fh = lane >> 4;

    for (int t = 0; t < NT; t++) {
        CP_WAIT_2();
        __syncthreads();

        const int lt = t + GSTAGES - 1;
        if (lt < NT) LOAD_STAGE(lt % GSTAGES, lt);
        CP_COMMIT();

        const uint32_t sb = sbase + (uint32_t)(t % GSTAGES) * STG_B;

        #pragma unroll
        for (int kk = 0; kk < 2; kk++) {
            const int chb = kk * 2 + fh;

            uint32_t aoff[4], boff[2];
            #pragma unroll
            for (int mi = 0; mi < 4; mi++) {
                const int row = wm * 64 + mi * 16 + fr;
                aoff[mi] = (uint32_t)row * 64 + (uint32_t)((chb ^ (row & 3)) << 4);
            }
            #pragma unroll
            for (int nj = 0; nj < 2; nj++) {
                const int row = wn * 32 + nj * 16 + fr;
                boff[nj] = (uint32_t)row * 64 + (uint32_t)((chb ^ (row & 3)) << 4);
            }

            uint32_t b[2][4];
            #pragma unroll
            for (int nj = 0; nj < 2; nj++)
                ldsm4(b[nj][0], b[nj][1], b[nj][2], b[nj][3],
                      sb + 16384u + boff[nj]);

            #pragma unroll
            for (int mi = 0; mi < 4; mi++) {
                uint32_t a0, a1, a2, a3;
                ldsm4(a0, a1, a2, a3, sb + aoff[mi]);
                mma16816h(c[mi][0], a0, a1, a2, a3, b[0][0], b[0][2]);
                mma16816h(c[mi][1], a0, a1, a2, a3, b[0][1], b[0][3]);
                mma16816h(c[mi][2], a0, a1, a2, a3, b[1][0], b[1][2]);
                mma16816h(c[mi][3], a0, a1, a2, a3, b[1][1], b[1][3]);
            }
            #pragma unroll
            for (int mi = 0; mi < 4; mi++) {
                uint32_t a0, a1, a2, a3;
                ldsm4(a0, a1, a2, a3, sb + 8192u + aoff[mi]);
                mma16816h(c[mi][0], a0, a1, a2, a3, b[0][0], b[0][2]);
                mma16816h(c[mi][1], a0, a1, a2, a3, b[0][1], b[0][3]);
                mma16816h(c[mi][2], a0, a1, a2, a3, b[1][0], b[1][2]);
                mma16816h(c[mi][3], a0, a1, a2, a3, b[1][1], b[1][3]);
            }
        }
    }

    const int q   = lane >> 2;
    const int rp  = lane & 3;
    const int m0g = by * BM + wm * 64;
    const int n0g = bx * BN + wn * 32;

    #pragma unroll
    for (int mi = 0; mi < 4; mi++) {
        #pragma unroll
        for (int ni = 0; ni < 4; ni++) {
            const int col = n0g + ni * 8 + rp * 2;
            const float bv0 = __ldg(bias + col);
            const float bv1 = __ldg(bias + col + 1);
            float v0 = c[mi][ni][0] + bv0;
            float v1 = c[mi][ni][1] + bv1;
            float v2 = c[mi][ni][2] + bv0;
            float v3 = c[mi][ni][3] + bv1;
            if (RELU) {
                v0 = fmaxf(v0, 0.0f); v1 = fmaxf(v1, 0.0f);
                v2 = fmaxf(v2, 0.0f); v3 = fmaxf(v3, 0.0f);
            }
            const int r0 = m0g + mi * 16 + q;
            const int r1 = r0 + 8;
            if (OUT_HALF) {
                unsigned int h, l;
                split2h(v0, v1, h, l);
                *(unsigned int*)(outhi + (size_t)r0 * DDIM + col) = h;
                *(unsigned int*)(outlo + (size_t)r0 * DDIM + col) = l;
                split2h(v2, v3, h, l);
                *(unsigned int*)(outhi + (size_t)r1 * DDIM + col) = h;
                *(unsigned int*)(outlo + (size_t)r1 * DDIM + col) = l;
            } else {
                *(float2*)(outf + (size_t)r0 * DDIM + col) = make_float2(v0, v1);
                *(float2*)(outf + (size_t)r1 * DDIM + col) = make_float2(v2, v3);
            }
        }
    }
    #undef LOAD_STAGE
}

// ---------------------------------------------------------------------------
// kernel_launch
// ---------------------------------------------------------------------------
extern "C" void kernel_launch(void* const* d_in, const int* in_sizes, int n_in,
                              void* d_out, int out_size)
{
    const float* x   = (const float*)d_in[0];
    const float* w1  = (const float*)d_in[1];
    const float* b1  = (const float*)d_in[2];
    const float* w2  = (const float*)d_in[3];
    const float* b2  = (const float*)d_in[4];
    const float* w3  = (const float*)d_in[5];
    const float* b3  = (const float*)d_in[6];
    const float* sw1 = (const float*)d_in[7];
    const float* sb1 = (const float*)d_in[8];
    const float* sw2 = (const float*)d_in[9];
    const float* sb2 = (const float*)d_in[10];
    const float* sw3 = (const float*)d_in[11];
    const float* sb3 = (const float*)d_in[12];
    float* out = (float*)d_out;

    const int M = in_sizes[0] / DDIM;   // 2048

    long long total = 0;
    for (int i = 7; i <= 12; i++) total += (long long)in_sizes[i];
    const unsigned int j = (unsigned int)(total / 2);

    const int nW4 = (DDIM * DDIM) / 4;
    const int nB4 = DDIM / 4;
    const int nX4 = (M * DDIM) / 4;

    // --- 1) exact global threshold: 2 full passes + compact + finish ---
    rs_init<<<1, 256>>>(j);
    rs_hist_p1<<<1024, 256>>>(sw1, nW4);
    rs_hist_p1<<<1024, 256>>>(sw2, nW4);
    rs_hist_p1<<<1024, 256>>>(sw3, nW4);
    rs_hist_p1<<<4,    256>>>(sb1, nB4);
    rs_hist_p1<<<4,    256>>>(sb2, nB4);
    rs_hist_p1<<<4,    256>>>(sb3, nB4);
    rs_scan<<<1, 256>>>(24);
    rs_hist_p2<<<1024, 256>>>(sw1, nW4);
    rs_hist_p2<<<1024, 256>>>(sw2, nW4);
    rs_hist_p2<<<1024, 256>>>(sw3, nW4);
    rs_hist_p2<<<4,    256>>>(sb1, nB4);
    rs_hist_p2<<<4,    256>>>(sb2, nB4);
    rs_hist_p2<<<4,    256>>>(sb3, nB4);
    rs_scan<<<1, 256>>>(16);
    rs_compact<<<1024, 256>>>(sw1, nW4);
    rs_compact<<<1024, 256>>>(sw2, nW4);
    rs_compact<<<1024, 256>>>(sw3, nW4);
    rs_compact<<<4,    256>>>(sb1, nB4);
    rs_compact<<<4,    256>>>(sb2, nB4);
    rs_compact<<<4,    256>>>(sb3, nB4);
    rs_final<<<1, 1024>>>();

    // --- scratch symbol addresses ---
    __half *pW1, *pW2, *pW3, *pXh, *pXl, *pH1h, *pH1l, *pH2h, *pH2l;
    float *pB1, *pB2, *pB3;
    cudaGetSymbolAddress((void**)&pW1,  g_W1h);
    cudaGetSymbolAddress((void**)&pW2,  g_W2h);
    cudaGetSymbolAddress((void**)&pW3,  g_W3h);
    cudaGetSymbolAddress((void**)&pXh,  g_Xhi);
    cudaGetSymbolAddress((void**)&pXl,  g_Xlo);
    cudaGetSymbolAddress((void**)&pH1h, g_H1hi);
    cudaGetSymbolAddress((void**)&pH1l, g_H1lo);
    cudaGetSymbolAddress((void**)&pH2h, g_H2hi);
    cudaGetSymbolAddress((void**)&pH2l, g_H2lo);
    cudaGetSymbolAddress((void**)&pB1,  g_B1);
    cudaGetSymbolAddress((void**)&pB2,  g_B2);
    cudaGetSymbolAddress((void**)&pB3,  g_B3);

    // --- 2) masked weights -> fp16 ; masked biases fp32 ; split x ---
    mask_half<<<1024, 256>>>(w1, sw1, pW1, nW4);
    mask_half<<<1024, 256>>>(w2, sw2, pW2, nW4);
    mask_half<<<1024, 256>>>(w3, sw3, pW3, nW4);
    mask_mul<<<4, 256>>>(b1, sb1, pB1, nB4);
    mask_mul<<<4, 256>>>(b2, sb2, pB2, nB4);
    mask_mul<<<4, 256>>>(b3, sb3, pB3, nB4);
    split_plain_h<<<1024, 256>>>(x, pXh, pXl, nX4);

    // --- 3) three dependent fp16 2-pass HMMA GEMMs ---
    cudaFuncSetAttribute(gemm_hmma<1, 1>,
                         cudaFuncAttributeMaxDynamicSharedMemorySize, GSMEM);
    cudaFuncSetAttribute(gemm_hmma<0, 0>,
                         cudaFuncAttributeMaxDynamicSharedMemorySize, GSMEM);

    dim3 grid(DDIM / BN, M / BM);       // (32, 16)
    gemm_hmma<1, 1><<<grid, 256, GSMEM>>>(pXh,  pXl,  pW1, pB1,
                                          nullptr, pH1h, pH1l);
    gemm_hmma<1, 1><<<grid, 256, GSMEM>>>(pH1h, pH1l, pW2, pB2,
                                          nullptr, pH2h, pH2l);
    gemm_hmma<0, 0><<<grid, 256, GSMEM>>>(pH2h, pH2l, pW3, pB3,
                                          out, nullptr, nullptr);

    (void)n_in; (void)out_size;
}

// round 11
// speedup vs baseline: 3.2778x; 1.0531x over previous
#include <cuda_runtime.h>
#include <cuda_bf16.h>
#include <cuda_fp16.h>
#include <cstdint>
#include <cstddef>

#define DDIM 4096
#define BATCH 2048
#define CAND_CAP (1u << 22)

// ---------------------------------------------------------------------------
// Device-global scratch
// ---------------------------------------------------------------------------
__device__ unsigned int g_hist[256];
__device__ unsigned int g_hist12[4096];
__device__ unsigned int g_prefix;
__device__ unsigned int g_krem;
__device__ float        g_thr;
__device__ unsigned int g_cand[CAND_CAP];
__device__ unsigned int g_cand_cnt;

__device__ __align__(128) __half g_W1h[(size_t)DDIM * DDIM];
__device__ __align__(128) __half g_W2h[(size_t)DDIM * DDIM];
__device__ __align__(128) __half g_W3h[(size_t)DDIM * DDIM];
__device__ __align__(128) __half g_Xhi[(size_t)BATCH * DDIM];
__device__ __align__(128) __half g_Xlo[(size_t)BATCH * DDIM];
__device__ __align__(128) __half g_H1hi[(size_t)BATCH * DDIM];
__device__ __align__(128) __half g_H1lo[(size_t)BATCH * DDIM];
__device__ __align__(128) __half g_H2hi[(size_t)BATCH * DDIM];
__device__ __align__(128) __half g_H2lo[(size_t)BATCH * DDIM];
__device__ float g_B1[DDIM];
__device__ float g_B2[DDIM];
__device__ float g_B3[DDIM];

// ---------------------------------------------------------------------------
// Radix select v3: 12-bit plain-atomic histogram (1 full pass) + compact
// (1 full pass) + cheap candidate-set passes for the remaining 20 bits.
// key = (u & 0x80000000) ? ~u : (u | 0x80000000)   (ascending float order)
// 12-bit bins: hottest bin <=~3% of data -> within-warp same-address
// collisions are rare -> plain smem atomics (no match_any needed).
// ---------------------------------------------------------------------------
__device__ __forceinline__ unsigned int f2key(float f)
{
    unsigned int u = __float_as_uint(f);
    return (u & 0x80000000u) ? ~u : (u | 0x80000000u);
}

__global__ void rs_init(unsigned int k)
{
    int t = threadIdx.x;   // 1024
    if (t < 256) g_hist[t] = 0u;
    for (int i = t; i < 4096; i += 1024) g_hist12[i] = 0u;
    if (t == 0) { g_prefix = 0u; g_krem = k; g_cand_cnt = 0u; }
}

// pass A: 12-bit histogram over full data, plain smem atomics
__global__ void rs_hist12(const float* __restrict__ p, int n4)
{
    __shared__ unsigned int sh[4096];
    for (int i = threadIdx.x; i < 4096; i += blockDim.x) sh[i] = 0u;
    __syncthreads();
    const float4* __restrict__ p4 = (const float4*)p;
    int i = blockIdx.x * blockDim.x + threadIdx.x;
    const int stride = gridDim.x * blockDim.x;
    for (; i < n4; i += stride) {
        float4 v = p4[i];
        atomicAdd(&sh[f2key(v.x) >> 20], 1u);
        atomicAdd(&sh[f2key(v.y) >> 20], 1u);
        atomicAdd(&sh[f2key(v.z) >> 20], 1u);
        atomicAdd(&sh[f2key(v.w) >> 20], 1u);
    }
    __syncthreads();
    for (int i2 = threadIdx.x; i2 < 4096; i2 += blockDim.x) {
        unsigned int cv = sh[i2];
        if (cv) atomicAdd(&g_hist12[i2], cv);
    }
}

// scan 4096 bins, pick bin containing rank g_krem, fold into prefix at shift
__global__ void rs_scan4096(int shift)
{
    __shared__ unsigned int s[1024];
    const int t = threadIdx.x;   // 1024
    unsigned int c0 = g_hist12[4 * t + 0];
    unsigned int c1 = g_hist12[4 * t + 1];
    unsigned int c2 = g_hist12[4 * t + 2];
    unsigned int c3 = g_hist12[4 * t + 3];
    g_hist12[4 * t + 0] = 0u; g_hist12[4 * t + 1] = 0u;
    g_hist12[4 * t + 2] = 0u; g_hist12[4 * t + 3] = 0u;
    const unsigned int sum = c0 + c1 + c2 + c3;
    s[t] = sum;
    __syncthreads();
    #pragma unroll
    for (int off = 1; off < 1024; off <<= 1) {
        unsigned int add = (t >= off) ? s[t - off] : 0u;
        __syncthreads();
        s[t] += add;
        __syncthreads();
    }
    const unsigned int inc = s[t];
    const unsigned int exc = inc - sum;
    const unsigned int k   = g_krem;
    if (k >= exc && k < inc) {
        unsigned int run = exc, bin;
        if      (k < run + c0) { bin = 4u * t + 0u; }
        else if (k < (run += c0) + c1) { bin = 4u * t + 1u; }
        else if (k < (run += c1) + c2) { bin = 4u * t + 2u; }
        else    { run += c2;    bin = 4u * t + 3u; }
        g_prefix |= bin << shift;
        g_krem    = k - run;
    }
}

// pass B: gather keys whose top 12 bits match the selected prefix
__global__ void rs_compact(const float* __restrict__ p, int n4)
{
    const unsigned int pref12 = g_prefix >> 20;
    const float4* __restrict__ p4 = (const float4*)p;
    int i = blockIdx.x * blockDim.x + threadIdx.x;
    const int stride = gridDim.x * blockDim.x;
    const int lane = threadIdx.x & 31;
    for (; i < n4; i += stride) {
        float4 v = p4[i];
        float arr[4] = {v.x, v.y, v.z, v.w};
        #pragma unroll
        for (int c = 0; c < 4; c++) {
            unsigned int key = f2key(arr[c]);
            bool m = (key >> 20) == pref12;
            unsigned int amask = __activemask();
            unsigned int bal = __ballot_sync(amask, m);
            if (m) {
                int leader = __ffs(bal) - 1;
                unsigned int base = 0;
                if (lane == leader)
                    base = atomicAdd(&g_cand_cnt, (unsigned int)__popc(bal));
                base = __shfl_sync(bal, base, leader);
                unsigned int idx = base + __popc(bal & ((1u << lane) - 1u));
                if (idx < CAND_CAP) g_cand[idx] = key;
            }
        }
    }
}

// pass C: 12-bit histogram of candidate bits [19:8]
__global__ void rs_hist12c()
{
    __shared__ unsigned int sh[4096];
    for (int i = threadIdx.x; i < 4096; i += blockDim.x) sh[i] = 0u;
    __syncthreads();
    unsigned int n = g_cand_cnt;
    if (n > CAND_CAP) n = CAND_CAP;
    unsigned int i = blockIdx.x * blockDim.x + threadIdx.x;
    const unsigned int stride = gridDim.x * blockDim.x;
    for (; i < n; i += stride)
        atomicAdd(&sh[(g_cand[i] >> 8) & 0xFFFu], 1u);
    __syncthreads();
    for (int i2 = threadIdx.x; i2 < 4096; i2 += blockDim.x) {
        unsigned int cv = sh[i2];
        if (cv) atomicAdd(&g_hist12[i2], cv);
    }
}

// pass D: 8-bit histogram of the last byte among candidates matching prefix>>8
__global__ void rs_histD()
{
    __shared__ unsigned int sh[256];
    for (int i = threadIdx.x; i < 256; i += blockDim.x) sh[i] = 0u;
    __syncthreads();
    const unsigned int pref24 = g_prefix >> 8;
    unsigned int n = g_cand_cnt;
    if (n > CAND_CAP) n = CAND_CAP;
    unsigned int i = blockIdx.x * blockDim.x + threadIdx.x;
    const unsigned int stride = gridDim.x * blockDim.x;
    for (; i < n; i += stride) {
        unsigned int key = g_cand[i];
        if ((key >> 8) == pref24) atomicAdd(&sh[key & 0xffu], 1u);
    }
    __syncthreads();
    for (int i2 = threadIdx.x; i2 < 256; i2 += blockDim.x) {
        unsigned int cv = sh[i2];
        if (cv) atomicAdd(&g_hist[i2], cv);
    }
}

__global__ void rs_pick()
{
    if (threadIdx.x == 0) {
        const unsigned int k = g_krem;
        unsigned int run = 0;
        for (int b = 0; b < 256; b++) {
            unsigned int c = g_hist[b];
            if (k < run + c) {
                unsigned int key = g_prefix | (unsigned int)b;
                unsigned int u = (key & 0x80000000u) ? (key ^ 0x80000000u) : ~key;
                g_thr = __uint_as_float(u);
                break;
            }
            run += c;
        }
    }
}

// ---------------------------------------------------------------------------
// fp16 split helpers + mask kernels
// ---------------------------------------------------------------------------
__device__ __forceinline__ void split2h(float f0, float f1,
                                        unsigned int& h, unsigned int& l)
{
    __half h0 = __float2half_rn(f0);
    __half h1 = __float2half_rn(f1);
    __half l0 = __float2half_rn(f0 - __half2float(h0));
    __half l1 = __float2half_rn(f1 - __half2float(h1));
    h = (unsigned int)__half_as_ushort(h0) |
        ((unsigned int)__half_as_ushort(h1) << 16);
    l = (unsigned int)__half_as_ushort(l0) |
        ((unsigned int)__half_as_ushort(l1) << 16);
}

__global__ void mask_half(const float* __restrict__ w,
                          const float* __restrict__ s,
                          __half* __restrict__ out, int n4)
{
    const float thr = g_thr;
    const float4* __restrict__ w4 = (const float4*)w;
    const float4* __restrict__ s4 = (const float4*)s;
    uint2* __restrict__ o2 = (uint2*)out;
    int i = blockIdx.x * blockDim.x + threadIdx.x;
    const int stride = gridDim.x * blockDim.x;
    for (; i < n4; i += stride) {
        float4 wv = w4[i];
        float4 sv = s4[i];
        float f0 = (sv.x >= thr) ? wv.x : 0.0f;
        float f1 = (sv.y >= thr) ? wv.y : 0.0f;
        float f2 = (sv.z >= thr) ? wv.z : 0.0f;
        float f3 = (sv.w >= thr) ? wv.w : 0.0f;
        uint2 o;
        o.x = (unsigned int)__half_as_ushort(__float2half_rn(f0)) |
              ((unsigned int)__half_as_ushort(__float2half_rn(f1)) << 16);
        o.y = (unsigned int)__half_as_ushort(__float2half_rn(f2)) |
              ((unsigned int)__half_as_ushort(__float2half_rn(f3)) << 16);
        o2[i] = o;
    }
}

__global__ void split_plain_h(const float* __restrict__ in,
                              __half* __restrict__ hi,
                              __half* __restrict__ lo, int n4)
{
    const float4* __restrict__ p4 = (const float4*)in;
    uint2* __restrict__ h2 = (uint2*)hi;
    uint2* __restrict__ l2 = (uint2*)lo;
    int i = blockIdx.x * blockDim.x + threadIdx.x;
    const int stride = gridDim.x * blockDim.x;
    for (; i < n4; i += stride) {
        float4 v = p4[i];
        uint2 hu, lu;
        split2h(v.x, v.y, hu.x, lu.x);
        split2h(v.z, v.w, hu.y, lu.y);
        h2[i] = hu;
        l2[i] = lu;
    }
}

__global__ void mask_mul(const float* __restrict__ w,
                         const float* __restrict__ s,
                         float* __restrict__ out, int n4)
{
    const float thr = g_thr;
    const float4* __restrict__ w4 = (const float4*)w;
    const float4* __restrict__ s4 = (const float4*)s;
    float4* __restrict__ o4 = (float4*)out;
    int i = blockIdx.x * blockDim.x + threadIdx.x;
    const int stride = gridDim.x * blockDim.x;
    for (; i < n4; i += stride) {
        float4 wv = w4[i];
        float4 sv = s4[i];
        float4 r;
        r.x = (sv.x >= thr) ? wv.x : 0.0f;
        r.y = (sv.y >= thr) ? wv.y : 0.0f;
        r.z = (sv.z >= thr) ? wv.z : 0.0f;
        r.w = (sv.w >= thr) ? wv.w : 0.0f;
        o4[i] = r;
    }
}

// ---------------------------------------------------------------------------
// cp.async + ldmatrix + mma.sync (fp16)
// ---------------------------------------------------------------------------
__device__ __forceinline__ uint32_t smem_u32(const void* p)
{
    uint32_t a;
    asm("{ .reg .u64 t; cvta.to.shared.u64 t, %1; cvt.u32.u64 %0, t; }"
        : "=r"(a) : "l"(p));
    return a;
}

__device__ __forceinline__ void cpasync16(uint32_t dst, const void* src)
{
    asm volatile("cp.async.cg.shared.global [%0], [%1], 16;"
                 :: "r"(dst), "l"(src) : "memory");
}
#define CP_COMMIT() asm volatile("cp.async.commit_group;" ::: "memory")
#define CP_WAIT_2() asm volatile("cp.async.wait_group 2;" ::: "memory")

__device__ __forceinline__ void ldsm4(uint32_t& r0, uint32_t& r1,
                                      uint32_t& r2, uint32_t& r3, uint32_t a)
{
    asm volatile("ldmatrix.sync.aligned.m8n8.x4.shared.b16 {%0,%1,%2,%3}, [%4];"
                 : "=r"(r0), "=r"(r1), "=r"(r2), "=r"(r3) : "r"(a));
}

__device__ __forceinline__ void mma16816h(float* c,
                                          uint32_t a0, uint32_t a1,
                                          uint32_t a2, uint32_t a3,
                                          uint32_t b0, uint32_t b1)
{
    asm volatile(
        "mma.sync.aligned.m16n8k16.row.col.f32.f16.f16.f32 "
        "{%0,%1,%2,%3}, {%4,%5,%6,%7}, {%8,%9}, {%0,%1,%2,%3};"
        : "+f"(c[0]), "+f"(c[1]), "+f"(c[2]), "+f"(c[3])
        : "r"(a0), "r"(a1), "r"(a2), "r"(a3), "r"(b0), "r"(b1));
}

// ---------------------------------------------------------------------------
// fp16 2-pass HMMA GEMM (unchanged from R10 baseline):
// C = Ahi@B^T + Alo@B^T + bias (opt ReLU); 4-stage cp.async; 2 CTAs/SM.
// ---------------------------------------------------------------------------
#define BM 128
#define BN 128
#define BK 32
#define GSTAGES 4
#define STG_B (3 * BM * BK * 2)        /* 24576 bytes per stage */
#define GSMEM  (GSTAGES * STG_B)       /* 98304 */

template<int RELU, int OUT_HALF>
__global__ void __launch_bounds__(256, 2) gemm_hmma(
    const __half* __restrict__ Ah, const __half* __restrict__ Al,
    const __half* __restrict__ B,
    const float* __restrict__ bias,
    float* __restrict__ outf,
    __half* __restrict__ outhi,
    __half* __restrict__ outlo)
{
    extern __shared__ __align__(128) char smem[];
    const uint32_t sbase = smem_u32(smem);
    const int tid  = threadIdx.x;
    const int lane = tid & 31;
    const int wid  = tid >> 5;
    const int wm   = wid >> 2;
    const int wn   = wid & 3;
    const int bx   = blockIdx.x;
    const int by   = blockIdx.y;
    const int K    = DDIM;

    const int lrow = tid >> 2;
    const int lch  = tid & 3;
    const uint32_t d0 = (uint32_t)lrow * 64 + (uint32_t)((lch ^ (lrow & 3)) << 4);

    const int rowA = by * BM;
    const int rowB = bx * BN;
    const __half* sAh0 = Ah + (size_t)(rowA + lrow) * K + lch * 8;
    const __half* sAh1 = Ah + (size_t)(rowA + lrow + 64) * K + lch * 8;
    const __half* sAl0 = Al + (size_t)(rowA + lrow) * K + lch * 8;
    const __half* sAl1 = Al + (size_t)(rowA + lrow + 64) * K + lch * 8;
    const __half* sB0  = B  + (size_t)(rowB + lrow) * K + lch * 8;
    const __half* sB1  = B  + (size_t)(rowB + lrow + 64) * K + lch * 8;

    #define LOAD_STAGE(stg, kt) do {                                          \
        const uint32_t s0 = sbase + (uint32_t)(stg) * STG_B + d0;             \
        const size_t ko = (size_t)(kt) * BK;                                  \
        cpasync16(s0,          sAh0 + ko);                                    \
        cpasync16(s0 + 4096,   sAh1 + ko);                                    \
        cpasync16(s0 + 8192,   sAl0 + ko);                                    \
        cpasync16(s0 + 12288,  sAl1 + ko);                                    \
        cpasync16(s0 + 16384,  sB0  + ko);                                    \
        cpasync16(s0 + 20480,  sB1  + ko);                                    \
    } while (0)

    float c[4][4][4];
    #pragma unroll
    for (int i = 0; i < 4; i++)
        #pragma unroll
        for (int j = 0; j < 4; j++)
            #pragma unroll
            for (int q = 0; q < 4; q++) c[i][j][q] = 0.0f;

    const int NT = K / BK;

    LOAD_STAGE(0, 0); CP_COMMIT();
    LOAD_STAGE(1, 1); CP_COMMIT();
    LOAD_STAGE(2, 2); CP_COMMIT();

    const int fr = lane & 15;
    const int fh = lane >> 4;

    for (int t = 0; t < NT; t++) {
        CP_WAIT_2();
        __syncthreads();

        const int lt = t + GSTAGES - 1;
        if (lt < NT) LOAD_STAGE(lt % GSTAGES, lt);
        CP_COMMIT();

        const uint32_t sb = sbase + (uint32_t)(t % GSTAGES) * STG_B;

        #pragma unroll
        for (int kk = 0; kk < 2; kk++) {
            const int chb = kk * 2 + fh;

            uint32_t aoff[4], boff[2];
            #pragma unroll
            for (int mi = 0; mi < 4; mi++) {
                const int row = wm * 64 + mi * 16 + fr;
                aoff[mi] = (uint32_t)row * 64 + (uint32_t)((chb ^ (row & 3)) << 4);
            }
            #pragma unroll
            for (int nj = 0; nj < 2; nj++) {
                const int row = wn * 32 + nj * 16 + fr;
                boff[nj] = (uint32_t)row * 64 + (uint32_t)((chb ^ (row & 3)) << 4);
            }

            uint32_t b[2][4];
            #pragma unroll
            for (int nj = 0; nj < 2; nj++)
                ldsm4(b[nj][0], b[nj][1], b[nj][2], b[nj][3],
                      sb + 16384u + boff[nj]);

            #pragma unroll
            for (int mi = 0; mi < 4; mi++) {
                uint32_t a0, a1, a2, a3;
                ldsm4(a0, a1, a2, a3, sb + aoff[mi]);
                mma16816h(c[mi][0], a0, a1, a2, a3, b[0][0], b[0][2]);
                mma16816h(c[mi][1], a0, a1, a2, a3, b[0][1], b[0][3]);
                mma16816h(c[mi][2], a0, a1, a2, a3, b[1][0], b[1][2]);
                mma16816h(c[mi][3], a0, a1, a2, a3, b[1][1], b[1][3]);
            }
            #pragma unroll
            for (int mi = 0; mi < 4; mi++) {
                uint32_t a0, a1, a2, a3;
                ldsm4(a0, a1, a2, a3, sb + 8192u + aoff[mi]);
                mma16816h(c[mi][0], a0, a1, a2, a3, b[0][0], b[0][2]);
                mma16816h(c[mi][1], a0, a1, a2, a3, b[0][1], b[0][3]);
                mma16816h(c[mi][2], a0, a1, a2, a3, b[1][0], b[1][2]);
                mma16816h(c[mi][3], a0, a1, a2, a3, b[1][1], b[1][3]);
            }
        }
    }

    const int q   = lane >> 2;
    const int rp  = lane & 3;
    const int m0g = by * BM + wm * 64;
    const int n0g = bx * BN + wn * 32;

    #pragma unroll
    for (int mi = 0; mi < 4; mi++) {
        #pragma unroll
        for (int ni = 0; ni < 4; ni++) {
            const int col = n0g + ni * 8 + rp * 2;
            const float bv0 = __ldg(bias + col);
            const float bv1 = __ldg(bias + col + 1);
            float v0 = c[mi][ni][0] + bv0;
            float v1 = c[mi][ni][1] + bv1;
            float v2 = c[mi][ni][2] + bv0;
            float v3 = c[mi][ni][3] + bv1;
            if (RELU) {
                v0 = fmaxf(v0, 0.0f); v1 = fmaxf(v1, 0.0f);
                v2 = fmaxf(v2, 0.0f); v3 = fmaxf(v3, 0.0f);
            }
            const int r0 = m0g + mi * 16 + q;
            const int r1 = r0 + 8;
            if (OUT_HALF) {
                unsigned int h, l;
                split2h(v0, v1, h, l);
                *(unsigned int*)(outhi + (size_t)r0 * DDIM + col) = h;
                *(unsigned int*)(outlo + (size_t)r0 * DDIM + col) = l;
                split2h(v2, v3, h, l);
                *(unsigned int*)(outhi + (size_t)r1 * DDIM + col) = h;
                *(unsigned int*)(outlo + (size_t)r1 * DDIM + col) = l;
            } else {
                *(float2*)(outf + (size_t)r0 * DDIM + col) = make_float2(v0, v1);
                *(float2*)(outf + (size_t)r1 * DDIM + col) = make_float2(v2, v3);
            }
        }
    }
    #undef LOAD_STAGE
}

// ---------------------------------------------------------------------------
// kernel_launch
// ---------------------------------------------------------------------------
extern "C" void kernel_launch(void* const* d_in, const int* in_sizes, int n_in,
                              void* d_out, int out_size)
{
    const float* x   = (const float*)d_in[0];
    const float* w1  = (const float*)d_in[1];
    const float* b1  = (const float*)d_in[2];
    const float* w2  = (const float*)d_in[3];
    const float* b2  = (const float*)d_in[4];
    const float* w3  = (const float*)d_in[5];
    const float* b3  = (const float*)d_in[6];
    const float* sw1 = (const float*)d_in[7];
    const float* sb1 = (const float*)d_in[8];
    const float* sw2 = (const float*)d_in[9];
    const float* sb2 = (const float*)d_in[10];
    const float* sw3 = (const float*)d_in[11];
    const float* sb3 = (const float*)d_in[12];
    float* out = (float*)d_out;

    const int M = in_sizes[0] / DDIM;   // 2048

    long long total = 0;
    for (int i = 7; i <= 12; i++) total += (long long)in_sizes[i];
    const unsigned int j = (unsigned int)(total / 2);

    const int nW4 = (DDIM * DDIM) / 4;
    const int nB4 = DDIM / 4;
    const int nX4 = (M * DDIM) / 4;

    // --- 1) exact global threshold: 12-bit hist + compact + tail passes ---
    rs_init<<<1, 1024>>>(j);
    rs_hist12<<<1024, 256>>>(sw1, nW4);
    rs_hist12<<<1024, 256>>>(sw2, nW4);
    rs_hist12<<<1024, 256>>>(sw3, nW4);
    rs_hist12<<<4,    256>>>(sb1, nB4);
    rs_hist12<<<4,    256>>>(sb2, nB4);
    rs_hist12<<<4,    256>>>(sb3, nB4);
    rs_scan4096<<<1, 1024>>>(20);
    rs_compact<<<1024, 256>>>(sw1, nW4);
    rs_compact<<<1024, 256>>>(sw2, nW4);
    rs_compact<<<1024, 256>>>(sw3, nW4);
    rs_compact<<<4,    256>>>(sb1, nB4);
    rs_compact<<<4,    256>>>(sb2, nB4);
    rs_compact<<<4,    256>>>(sb3, nB4);
    rs_hist12c<<<256, 256>>>();
    rs_scan4096<<<1, 1024>>>(8);
    rs_histD<<<64, 256>>>();
    rs_pick<<<1, 32>>>();

    // --- scratch symbol addresses ---
    __half *pW1, *pW2, *pW3, *pXh, *pXl, *pH1h, *pH1l, *pH2h, *pH2l;
    float *pB1, *pB2, *pB3;
    cudaGetSymbolAddress((void**)&pW1,  g_W1h);
    cudaGetSymbolAddress((void**)&pW2,  g_W2h);
    cudaGetSymbolAddress((void**)&pW3,  g_W3h);
    cudaGetSymbolAddress((void**)&pXh,  g_Xhi);
    cudaGetSymbolAddress((void**)&pXl,  g_Xlo);
    cudaGetSymbolAddress((void**)&pH1h, g_H1hi);
    cudaGetSymbolAddress((void**)&pH1l, g_H1lo);
    cudaGetSymbolAddress((void**)&pH2h, g_H2hi);
    cudaGetSymbolAddress((void**)&pH2l, g_H2lo);
    cudaGetSymbolAddress((void**)&pB1,  g_B1);
    cudaGetSymbolAddress((void**)&pB2,  g_B2);
    cudaGetSymbolAddress((void**)&pB3,  g_B3);

    // --- 2) masked weights -> fp16 ; masked biases fp32 ; split x ---
    mask_half<<<1024, 256>>>(w1, sw1, pW1, nW4);
    mask_half<<<1024, 256>>>(w2, sw2, pW2, nW4);
    mask_half<<<1024, 256>>>(w3, sw3, pW3, nW4);
    mask_mul<<<4, 256>>>(b1, sb1, pB1, nB4);
    mask_mul<<<4, 256>>>(b2, sb2, pB2, nB4);
    mask_mul<<<4, 256>>>(b3, sb3, pB3, nB4);
    split_plain_h<<<1024, 256>>>(x, pXh, pXl, nX4);

    // --- 3) three dependent fp16 2-pass HMMA GEMMs ---
    cudaFuncSetAttribute(gemm_hmma<1, 1>,
                         cudaFuncAttributeMaxDynamicSharedMemorySize, GSMEM);
    cudaFuncSetAttribute(gemm_hmma<0, 0>,
                         cudaFuncAttributeMaxDynamicSharedMemorySize, GSMEM);

    dim3 grid(DDIM / BN, M / BM);       // (32, 16)
    gemm_hmma<1, 1><<<grid, 256, GSMEM>>>(pXh,  pXl,  pW1, pB1,
                                          nullptr, pH1h, pH1l);
    gemm_hmma<1, 1><<<grid, 256, GSMEM>>>(pH1h, pH1l, pW2, pB2,
                                          nullptr, pH2h, pH2l);
    gemm_hmma<0, 0><<<grid, 256, GSMEM>>>(pH2h, pH2l, pW3, pB3,
                                          out, nullptr, nullptr);

    (void)n_in; (void)out_size;
}

// round 12
// speedup vs baseline: 3.3476x; 1.0213x over previous
#include <cuda_runtime.h>
#include <cuda_bf16.h>
#include <cuda_fp16.h>
#include <cstdint>
#include <cstddef>

#define DDIM 4096
#define BATCH 2048
#define CAND_CAP (1u << 22)

// ---------------------------------------------------------------------------
// Device-global scratch
// ---------------------------------------------------------------------------
__device__ unsigned int g_hist[256];
__device__ unsigned int g_hist12[4096];
__device__ unsigned int g_prefix;
__device__ unsigned int g_krem;
__device__ float        g_thr;
__device__ unsigned int g_cand[CAND_CAP];
__device__ unsigned int g_cand_cnt;

__device__ __align__(128) __half g_W1h[(size_t)DDIM * DDIM];
__device__ __align__(128) __half g_W2h[(size_t)DDIM * DDIM];
__device__ __align__(128) __half g_W3h[(size_t)DDIM * DDIM];
__device__ __align__(128) __half g_Xhi[(size_t)BATCH * DDIM];
__device__ __align__(128) __half g_Xlo[(size_t)BATCH * DDIM];
__device__ __align__(128) __half g_H1hi[(size_t)BATCH * DDIM];
__device__ __align__(128) __half g_H1lo[(size_t)BATCH * DDIM];
__device__ __align__(128) __half g_H2hi[(size_t)BATCH * DDIM];
__device__ __align__(128) __half g_H2lo[(size_t)BATCH * DDIM];
__device__ float g_B1[DDIM];
__device__ float g_B2[DDIM];
__device__ float g_B3[DDIM];

// ---------------------------------------------------------------------------
// Radix select v3 (R11-verified): 12-bit plain-atomic histogram (1 full pass)
// + compact (1 full pass) + cheap candidate-set passes for remaining 20 bits.
// key = (u & 0x80000000) ? ~u : (u | 0x80000000)   (ascending float order)
// ---------------------------------------------------------------------------
__device__ __forceinline__ unsigned int f2key(float f)
{
    unsigned int u = __float_as_uint(f);
    return (u & 0x80000000u) ? ~u : (u | 0x80000000u);
}

__global__ void rs_init(unsigned int k)
{
    int t = threadIdx.x;   // 1024
    if (t < 256) g_hist[t] = 0u;
    for (int i = t; i < 4096; i += 1024) g_hist12[i] = 0u;
    if (t == 0) { g_prefix = 0u; g_krem = k; g_cand_cnt = 0u; }
}

// pass A: 12-bit histogram over full data, plain smem atomics
__global__ void rs_hist12(const float* __restrict__ p, int n4)
{
    __shared__ unsigned int sh[4096];
    for (int i = threadIdx.x; i < 4096; i += blockDim.x) sh[i] = 0u;
    __syncthreads();
    const float4* __restrict__ p4 = (const float4*)p;
    int i = blockIdx.x * blockDim.x + threadIdx.x;
    const int stride = gridDim.x * blockDim.x;
    for (; i < n4; i += stride) {
        float4 v = p4[i];
        atomicAdd(&sh[f2key(v.x) >> 20], 1u);
        atomicAdd(&sh[f2key(v.y) >> 20], 1u);
        atomicAdd(&sh[f2key(v.z) >> 20], 1u);
        atomicAdd(&sh[f2key(v.w) >> 20], 1u);
    }
    __syncthreads();
    for (int i2 = threadIdx.x; i2 < 4096; i2 += blockDim.x) {
        unsigned int cv = sh[i2];
        if (cv) atomicAdd(&g_hist12[i2], cv);
    }
}

// scan 4096 bins, pick bin containing rank g_krem, fold into prefix at shift
__global__ void rs_scan4096(int shift)
{
    __shared__ unsigned int s[1024];
    const int t = threadIdx.x;   // 1024
    unsigned int c0 = g_hist12[4 * t + 0];
    unsigned int c1 = g_hist12[4 * t + 1];
    unsigned int c2 = g_hist12[4 * t + 2];
    unsigned int c3 = g_hist12[4 * t + 3];
    g_hist12[4 * t + 0] = 0u; g_hist12[4 * t + 1] = 0u;
    g_hist12[4 * t + 2] = 0u; g_hist12[4 * t + 3] = 0u;
    const unsigned int sum = c0 + c1 + c2 + c3;
    s[t] = sum;
    __syncthreads();
    #pragma unroll
    for (int off = 1; off < 1024; off <<= 1) {
        unsigned int add = (t >= off) ? s[t - off] : 0u;
        __syncthreads();
        s[t] += add;
        __syncthreads();
    }
    const unsigned int inc = s[t];
    const unsigned int exc = inc - sum;
    const unsigned int k   = g_krem;
    if (k >= exc && k < inc) {
        unsigned int run = exc, bin;
        if      (k < run + c0) { bin = 4u * t + 0u; }
        else if (k < (run += c0) + c1) { bin = 4u * t + 1u; }
        else if (k < (run += c1) + c2) { bin = 4u * t + 2u; }
        else    { run += c2;    bin = 4u * t + 3u; }
        g_prefix |= bin << shift;
        g_krem    = k - run;
    }
}

// pass B: gather keys whose top 12 bits match the selected prefix (2-way ILP)
__global__ void rs_compact(const float* __restrict__ p, int n4)
{
    const unsigned int pref12 = g_prefix >> 20;
    const float4* __restrict__ p4 = (const float4*)p;
    const int stride = gridDim.x * blockDim.x;
    int i = blockIdx.x * blockDim.x + threadIdx.x;
    const int lane = threadIdx.x & 31;
    for (; i < n4; i += 2 * stride) {
        float4 v0 = p4[i];
        const bool has2 = (i + stride) < n4;
        float4 v1 = has2 ? p4[i + stride] : make_float4(0, 0, 0, 0);
        float arr[8] = {v0.x, v0.y, v0.z, v0.w, v1.x, v1.y, v1.z, v1.w};
        const int cnt = has2 ? 8 : 4;
        for (int c = 0; c < cnt; c++) {
            unsigned int key = f2key(arr[c]);
            bool m = (key >> 20) == pref12;
            unsigned int amask = __activemask();
            unsigned int bal = __ballot_sync(amask, m);
            if (m) {
                int leader = __ffs(bal) - 1;
                unsigned int base = 0;
                if (lane == leader)
                    base = atomicAdd(&g_cand_cnt, (unsigned int)__popc(bal));
                base = __shfl_sync(bal, base, leader);
                unsigned int idx = base + __popc(bal & ((1u << lane) - 1u));
                if (idx < CAND_CAP) g_cand[idx] = key;
            }
        }
    }
}

// pass C: 12-bit histogram of candidate bits [19:8]
__global__ void rs_hist12c()
{
    __shared__ unsigned int sh[4096];
    for (int i = threadIdx.x; i < 4096; i += blockDim.x) sh[i] = 0u;
    __syncthreads();
    unsigned int n = g_cand_cnt;
    if (n > CAND_CAP) n = CAND_CAP;
    unsigned int i = blockIdx.x * blockDim.x + threadIdx.x;
    const unsigned int stride = gridDim.x * blockDim.x;
    for (; i < n; i += stride)
        atomicAdd(&sh[(g_cand[i] >> 8) & 0xFFFu], 1u);
    __syncthreads();
    for (int i2 = threadIdx.x; i2 < 4096; i2 += blockDim.x) {
        unsigned int cv = sh[i2];
        if (cv) atomicAdd(&g_hist12[i2], cv);
    }
}

// pass D: 8-bit histogram of the last byte among candidates matching prefix>>8
__global__ void rs_histD()
{
    __shared__ unsigned int sh[256];
    for (int i = threadIdx.x; i < 256; i += blockDim.x) sh[i] = 0u;
    __syncthreads();
    const unsigned int pref24 = g_prefix >> 8;
    unsigned int n = g_cand_cnt;
    if (n > CAND_CAP) n = CAND_CAP;
    unsigned int i = blockIdx.x * blockDim.x + threadIdx.x;
    const unsigned int stride = gridDim.x * blockDim.x;
    for (; i < n; i += stride) {
        unsigned int key = g_cand[i];
        if ((key >> 8) == pref24) atomicAdd(&sh[key & 0xffu], 1u);
    }
    __syncthreads();
    for (int i2 = threadIdx.x; i2 < 256; i2 += blockDim.x) {
        unsigned int cv = sh[i2];
        if (cv) atomicAdd(&g_hist[i2], cv);
    }
}

__global__ void rs_pick()
{
    if (threadIdx.x == 0) {
        const unsigned int k = g_krem;
        unsigned int run = 0;
        for (int b = 0; b < 256; b++) {
            unsigned int c = g_hist[b];
            if (k < run + c) {
                unsigned int key = g_prefix | (unsigned int)b;
                unsigned int u = (key & 0x80000000u) ? (key ^ 0x80000000u) : ~key;
                g_thr = __uint_as_float(u);
                break;
            }
            run += c;
        }
    }
}

// ---------------------------------------------------------------------------
// fp16 split helpers + mask kernels
// ---------------------------------------------------------------------------
__device__ __forceinline__ void split2h(float f0, float f1,
                                        unsigned int& h, unsigned int& l)
{
    __half h0 = __float2half_rn(f0);
    __half h1 = __float2half_rn(f1);
    __half l0 = __float2half_rn(f0 - __half2float(h0));
    __half l1 = __float2half_rn(f1 - __half2float(h1));
    h = (unsigned int)__half_as_ushort(h0) |
        ((unsigned int)__half_as_ushort(h1) << 16);
    l = (unsigned int)__half_as_ushort(l0) |
        ((unsigned int)__half_as_ushort(l1) << 16);
}

__global__ void mask_half(const float* __restrict__ w,
                          const float* __restrict__ s,
                          __half* __restrict__ out, int n4)
{
    const float thr = g_thr;
    const float4* __restrict__ w4 = (const float4*)w;
    const float4* __restrict__ s4 = (const float4*)s;
    uint2* __restrict__ o2 = (uint2*)out;
    int i = blockIdx.x * blockDim.x + threadIdx.x;
    const int stride = gridDim.x * blockDim.x;
    for (; i < n4; i += stride) {
        float4 wv = w4[i];
        float4 sv = s4[i];
        float f0 = (sv.x >= thr) ? wv.x : 0.0f;
        float f1 = (sv.y >= thr) ? wv.y : 0.0f;
        float f2 = (sv.z >= thr) ? wv.z : 0.0f;
        float f3 = (sv.w >= thr) ? wv.w : 0.0f;
        uint2 o;
        o.x = (unsigned int)__half_as_ushort(__float2half_rn(f0)) |
              ((unsigned int)__half_as_ushort(__float2half_rn(f1)) << 16);
        o.y = (unsigned int)__half_as_ushort(__float2half_rn(f2)) |
              ((unsigned int)__half_as_ushort(__float2half_rn(f3)) << 16);
        o2[i] = o;
    }
}

__global__ void split_plain_h(const float* __restrict__ in,
                              __half* __restrict__ hi,
                              __half* __restrict__ lo, int n4)
{
    const float4* __restrict__ p4 = (const float4*)in;
    uint2* __restrict__ h2 = (uint2*)hi;
    uint2* __restrict__ l2 = (uint2*)lo;
    int i = blockIdx.x * blockDim.x + threadIdx.x;
    const int stride = gridDim.x * blockDim.x;
    for (; i < n4; i += stride) {
        float4 v = p4[i];
        uint2 hu, lu;
        split2h(v.x, v.y, hu.x, lu.x);
        split2h(v.z, v.w, hu.y, lu.y);
        h2[i] = hu;
        l2[i] = lu;
    }
}

__global__ void mask_mul(const float* __restrict__ w,
                         const float* __restrict__ s,
                         float* __restrict__ out, int n4)
{
    const float thr = g_thr;
    const float4* __restrict__ w4 = (const float4*)w;
    const float4* __restrict__ s4 = (const float4*)s;
    float4* __restrict__ o4 = (float4*)out;
    int i = blockIdx.x * blockDim.x + threadIdx.x;
    const int stride = gridDim.x * blockDim.x;
    for (; i < n4; i += stride) {
        float4 wv = w4[i];
        float4 sv = s4[i];
        float4 r;
        r.x = (sv.x >= thr) ? wv.x : 0.0f;
        r.y = (sv.y >= thr) ? wv.y : 0.0f;
        r.z = (sv.z >= thr) ? wv.z : 0.0f;
        r.w = (sv.w >= thr) ? wv.w : 0.0f;
        o4[i] = r;
    }
}

// ---------------------------------------------------------------------------
// cp.async + ldmatrix + mma.sync (fp16)
// ---------------------------------------------------------------------------
__device__ __forceinline__ uint32_t smem_u32(const void* p)
{
    uint32_t a;
    asm("{ .reg .u64 t; cvta.to.shared.u64 t, %1; cvt.u32.u64 %0, t; }"
        : "=r"(a) : "l"(p));
    return a;
}

__device__ __forceinline__ void cpasync16(uint32_t dst, const void* src)
{
    asm volatile("cp.async.cg.shared.global [%0], [%1], 16;"
                 :: "r"(dst), "l"(src) : "memory");
}
#define CP_COMMIT() asm volatile("cp.async.commit_group;" ::: "memory")
#define CP_WAIT_2() asm volatile("cp.async.wait_group 2;" ::: "memory")

__device__ __forceinline__ void ldsm4(uint32_t& r0, uint32_t& r1,
                                      uint32_t& r2, uint32_t& r3, uint32_t a)
{
    asm volatile("ldmatrix.sync.aligned.m8n8.x4.shared.b16 {%0,%1,%2,%3}, [%4];"
                 : "=r"(r0), "=r"(r1), "=r"(r2), "=r"(r3) : "r"(a));
}

__device__ __forceinline__ void mma16816h(float* c,
                                          uint32_t a0, uint32_t a1,
                                          uint32_t a2, uint32_t a3,
                                          uint32_t b0, uint32_t b1)
{
    asm volatile(
        "mma.sync.aligned.m16n8k16.row.col.f32.f16.f16.f32 "
        "{%0,%1,%2,%3}, {%4,%5,%6,%7}, {%8,%9}, {%0,%1,%2,%3};"
        : "+f"(c[0]), "+f"(c[1]), "+f"(c[2]), "+f"(c[3])
        : "r"(a0), "r"(a1), "r"(a2), "r"(a3), "r"(b0), "r"(b1));
}

// ---------------------------------------------------------------------------
// fp16 2-pass HMMA GEMM: C = Ahi@B^T + Alo@B^T + bias (opt ReLU)
// 4-stage cp.async (prefetch depth 2); 2 CTAs/SM.
// Warp layout 4(M) x 2(N): warp tile 32x64 -> 8 ldsm4 / 32 mma per k-chunk
// (was 10 with the 64x32 tile): B fragments (4 ldsm) reused across both
// passes; A hi/lo are 2 ldsm each.
// ---------------------------------------------------------------------------
#define BM 128
#define BN 128
#define BK 32
#define GSTAGES 4
#define STG_B (3 * BM * BK * 2)        /* 24576 bytes per stage */
#define GSMEM  (GSTAGES * STG_B)       /* 98304 */

template<int RELU, int OUT_HALF>
__global__ void __launch_bounds__(256, 2) gemm_hmma(
    const __half* __restrict__ Ah, const __half* __restrict__ Al,
    const __half* __restrict__ B,
    const float* __restrict__ bias,
    float* __restrict__ outf,
    __half* __restrict__ outhi,
    __half* __restrict__ outlo)
{
    extern __shared__ __align__(128) char smem[];
    const uint32_t sbase = smem_u32(smem);
    const int tid  = threadIdx.x;
    const int lane = tid & 31;
    const int wid  = tid >> 5;
    const int wm   = wid >> 1;          // 0..3  (M group, 32 rows each)
    const int wn   = wid & 1;           // 0..1  (N group, 64 cols each)
    const int bx   = blockIdx.x;        // N tile
    const int by   = blockIdx.y;        // M tile
    const int K    = DDIM;

    const int lrow = tid >> 2;          // 0..63
    const int lch  = tid & 3;           // 16B chunk within 64B row
    const uint32_t d0 = (uint32_t)lrow * 64 + (uint32_t)((lch ^ (lrow & 3)) << 4);

    const int rowA = by * BM;
    const int rowB = bx * BN;
    const __half* sAh0 = Ah + (size_t)(rowA + lrow) * K + lch * 8;
    const __half* sAh1 = Ah + (size_t)(rowA + lrow + 64) * K + lch * 8;
    const __half* sAl0 = Al + (size_t)(rowA + lrow) * K + lch * 8;
    const __half* sAl1 = Al + (size_t)(rowA + lrow + 64) * K + lch * 8;
    const __half* sB0  = B  + (size_t)(rowB + lrow) * K + lch * 8;
    const __half* sB1  = B  + (size_t)(rowB + lrow + 64) * K + lch * 8;

    #define LOAD_STAGE(stg, kt) do {                                          \
        const uint32_t s0 = sbase + (uint32_t)(stg) * STG_B + d0;             \
        const size_t ko = (size_t)(kt) * BK;                                  \
        cpasync16(s0,          sAh0 + ko);                                    \
        cpasync16(s0 + 4096,   sAh1 + ko);                                    \
        cpasync16(s0 + 8192,   sAl0 + ko);                                    \
        cpasync16(s0 + 12288,  sAl1 + ko);                                    \
        cpasync16(s0 + 16384,  sB0  + ko);                                    \
        cpasync16(s0 + 20480,  sB1  + ko);                                    \
    } while (0)

    float c[2][8][4];
    #pragma unroll
    for (int i = 0; i < 2; i++)
        #pragma unroll
        for (int j = 0; j < 8; j++)
            #pragma unroll
            for (int q = 0; q < 4; q++) c[i][j][q] = 0.0f;

    const int NT = K / BK;              // 128

    LOAD_STAGE(0, 0); CP_COMMIT();
    LOAD_STAGE(1, 1); CP_COMMIT();
    LOAD_STAGE(2, 2); CP_COMMIT();

    const int fr = lane & 15;
    const int fh = lane >> 4;

    for (int t = 0; t < NT; t++) {
        CP_WAIT_2();
        __syncthreads();

        const int lt = t + GSTAGES - 1;
        if (lt < NT) LOAD_STAGE(lt % GSTAGES, lt);
        CP_COMMIT();

        const uint32_t sb = sbase + (uint32_t)(t % GSTAGES) * STG_B;

        #pragma unroll
        for (int kk = 0; kk < 2; kk++) {
            const int chb = kk * 2 + fh;

            uint32_t aoff[2], boff[4];
            #pragma unroll
            for (int mi = 0; mi < 2; mi++) {
                const int row = wm * 32 + mi * 16 + fr;
                aoff[mi] = (uint32_t)row * 64 + (uint32_t)((chb ^ (row & 3)) << 4);
            }
            #pragma unroll
            for (int nj = 0; nj < 4; nj++) {
                const int row = wn * 64 + nj * 16 + fr;
                boff[nj] = (uint32_t)row * 64 + (uint32_t)((chb ^ (row & 3)) << 4);
            }

            // B fragments loaded once, reused for both passes
            uint32_t b[4][4];
            #pragma unroll
            for (int nj = 0; nj < 4; nj++)
                ldsm4(b[nj][0], b[nj][1], b[nj][2], b[nj][3],
                      sb + 16384u + boff[nj]);

            // pass 1: Ahi x B
            #pragma unroll
            for (int mi = 0; mi < 2; mi++) {
                uint32_t a0, a1, a2, a3;
                ldsm4(a0, a1, a2, a3, sb + aoff[mi]);
                #pragma unroll
                for (int nj = 0; nj < 4; nj++) {
                    mma16816h(c[mi][2 * nj + 0], a0, a1, a2, a3,
                              b[nj][0], b[nj][2]);
                    mma16816h(c[mi][2 * nj + 1], a0, a1, a2, a3,
                              b[nj][1], b[nj][3]);
                }
            }
            // pass 2: Alo x B (reuse B fragments)
            #pragma unroll
            for (int mi = 0; mi < 2; mi++) {
                uint32_t a0, a1, a2, a3;
                ldsm4(a0, a1, a2, a3, sb + 8192u + aoff[mi]);
                #pragma unroll
                for (int nj = 0; nj < 4; nj++) {
                    mma16816h(c[mi][2 * nj + 0], a0, a1, a2, a3,
                              b[nj][0], b[nj][2]);
                    mma16816h(c[mi][2 * nj + 1], a0, a1, a2, a3,
                              b[nj][1], b[nj][3]);
                }
            }
        }
    }

    // --- epilogue: bias (+ReLU), then fp32 store or fp16 hi/lo re-split ---
    const int q   = lane >> 2;          // 0..7
    const int rp  = lane & 3;           // column pair
    const int m0g = by * BM + wm * 32;
    const int n0g = bx * BN + wn * 64;

    #pragma unroll
    for (int mi = 0; mi < 2; mi++) {
        #pragma unroll
        for (int ni = 0; ni < 8; ni++) {
            const int col = n0g + ni * 8 + rp * 2;
            const float bv0 = __ldg(bias + col);
            const float bv1 = __ldg(bias + col + 1);
            float v0 = c[mi][ni][0] + bv0;
            float v1 = c[mi][ni][1] + bv1;
            float v2 = c[mi][ni][2] + bv0;
            float v3 = c[mi][ni][3] + bv1;
            if (RELU) {
                v0 = fmaxf(v0, 0.0f); v1 = fmaxf(v1, 0.0f);
                v2 = fmaxf(v2, 0.0f); v3 = fmaxf(v3, 0.0f);
            }
            const int r0 = m0g + mi * 16 + q;
            const int r1 = r0 + 8;
            if (OUT_HALF) {
                unsigned int h, l;
                split2h(v0, v1, h, l);
                *(unsigned int*)(outhi + (size_t)r0 * DDIM + col) = h;
                *(unsigned int*)(outlo + (size_t)r0 * DDIM + col) = l;
                split2h(v2, v3, h, l);
                *(unsigned int*)(outhi + (size_t)r1 * DDIM + col) = h;
                *(unsigned int*)(outlo + (size_t)r1 * DDIM + col) = l;
            } else {
                *(float2*)(outf + (size_t)r0 * DDIM + col) = make_float2(v0, v1);
                *(float2*)(outf + (size_t)r1 * DDIM + col) = make_float2(v2, v3);
            }
        }
    }
    #undef LOAD_STAGE
}

// ---------------------------------------------------------------------------
// kernel_launch
// ---------------------------------------------------------------------------
extern "C" void kernel_launch(void* const* d_in, const int* in_sizes, int n_in,
                              void* d_out, int out_size)
{
    const float* x   = (const float*)d_in[0];
    const float* w1  = (const float*)d_in[1];
    const float* b1  = (const float*)d_in[2];
    const float* w2  = (const float*)d_in[3];
    const float* b2  = (const float*)d_in[4];
    const float* w3  = (const float*)d_in[5];
    const float* b3  = (const float*)d_in[6];
    const float* sw1 = (const float*)d_in[7];
    const float* sb1 = (const float*)d_in[8];
    const float* sw2 = (const float*)d_in[9];
    const float* sb2 = (const float*)d_in[10];
    const float* sw3 = (const float*)d_in[11];
    const float* sb3 = (const float*)d_in[12];
    float* out = (float*)d_out;

    const int M = in_sizes[0] / DDIM;   // 2048

    long long total = 0;
    for (int i = 7; i <= 12; i++) total += (long long)in_sizes[i];
    const unsigned int j = (unsigned int)(total / 2);

    const int nW4 = (DDIM * DDIM) / 4;
    const int nB4 = DDIM / 4;
    const int nX4 = (M * DDIM) / 4;

    // --- 1) exact global threshold: 12-bit hist + compact + tail passes ---
    rs_init<<<1, 1024>>>(j);
    rs_hist12<<<1024, 256>>>(sw1, nW4);
    rs_hist12<<<1024, 256>>>(sw2, nW4);
    rs_hist12<<<1024, 256>>>(sw3, nW4);
    rs_hist12<<<4,    256>>>(sb1, nB4);
    rs_hist12<<<4,    256>>>(sb2, nB4);
    rs_hist12<<<4,    256>>>(sb3, nB4);
    rs_scan4096<<<1, 1024>>>(20);
    rs_compact<<<1024, 256>>>(sw1, nW4);
    rs_compact<<<1024, 256>>>(sw2, nW4);
    rs_compact<<<1024, 256>>>(sw3, nW4);
    rs_compact<<<4,    256>>>(sb1, nB4);
    rs_compact<<<4,    256>>>(sb2, nB4);
    rs_compact<<<4,    256>>>(sb3, nB4);
    rs_hist12c<<<256, 256>>>();
    rs_scan4096<<<1, 1024>>>(8);
    rs_histD<<<64, 256>>>();
    rs_pick<<<1, 32>>>();

    // --- scratch symbol addresses ---
    __half *pW1, *pW2, *pW3, *pXh, *pXl, *pH1h, *pH1l, *pH2h, *pH2l;
    float *pB1, *pB2, *pB3;
    cudaGetSymbolAddress((void**)&pW1,  g_W1h);
    cudaGetSymbolAddress((void**)&pW2,  g_W2h);
    cudaGetSymbolAddress((void**)&pW3,  g_W3h);
    cudaGetSymbolAddress((void**)&pXh,  g_Xhi);
    cudaGetSymbolAddress((void**)&pXl,  g_Xlo);
    cudaGetSymbolAddress((void**)&pH1h, g_H1hi);
    cudaGetSymbolAddress((void**)&pH1l, g_H1lo);
    cudaGetSymbolAddress((void**)&pH2h, g_H2hi);
    cudaGetSymbolAddress((void**)&pH2l, g_H2lo);
    cudaGetSymbolAddress((void**)&pB1,  g_B1);
    cudaGetSymbolAddress((void**)&pB2,  g_B2);
    cudaGetSymbolAddress((void**)&pB3,  g_B3);

    // --- 2) masked weights -> fp16 ; masked biases fp32 ; split x ---
    mask_half<<<1024, 256>>>(w1, sw1, pW1, nW4);
    mask_half<<<1024, 256>>>(w2, sw2, pW2, nW4);
    mask_half<<<1024, 256>>>(w3, sw3, pW3, nW4);
    mask_mul<<<4, 256>>>(b1, sb1, pB1, nB4);
    mask_mul<<<4, 256>>>(b2, sb2, pB2, nB4);
    mask_mul<<<4, 256>>>(b3, sb3, pB3, nB4);
    split_plain_h<<<1024, 256>>>(x, pXh, pXl, nX4);

    // --- 3) three dependent fp16 2-pass HMMA GEMMs ---
    cudaFuncSetAttribute(gemm_hmma<1, 1>,
                         cudaFuncAttributeMaxDynamicSharedMemorySize, GSMEM);
    cudaFuncSetAttribute(gemm_hmma<0, 0>,
                         cudaFuncAttributeMaxDynamicSharedMemorySize, GSMEM);

    dim3 grid(DDIM / BN, M / BM);       // (32, 16)
    gemm_hmma<1, 1><<<grid, 256, GSMEM>>>(pXh,  pXl,  pW1, pB1,
                                          nullptr, pH1h, pH1l);
    gemm_hmma<1, 1><<<grid, 256, GSMEM>>>(pH1h, pH1l, pW2, pB2,
                                          nullptr, pH2h, pH2l);
    gemm_hmma<0, 0><<<grid, 256, GSMEM>>>(pH2h, pH2l, pW3, pB3,
                                          out, nullptr, nullptr);

    (void)n_in; (void)out_size;
}

// round 13
// speedup vs baseline: 5.3954x; 1.6117x over previous
#include <cuda_runtime.h>
#include <cuda_bf16.h>
#include <cuda_fp16.h>
#include <cstdint>
#include <cstddef>

#define DDIM 4096
#define BATCH 2048
#define CAND_CAP (1u << 22)

// ---------------------------------------------------------------------------
// Device-global scratch
// ---------------------------------------------------------------------------
__device__ unsigned int g_hist[256];
__device__ unsigned int g_hist12[4096];
__device__ unsigned int g_prefix;
__device__ unsigned int g_krem;
__device__ float        g_thr;
__device__ unsigned int g_cand[CAND_CAP];
__device__ unsigned int g_cand_cnt;

__device__ __align__(128) __half g_W1h[(size_t)DDIM * DDIM];
__device__ __align__(128) __half g_W2h[(size_t)DDIM * DDIM];
__device__ __align__(128) __half g_W3h[(size_t)DDIM * DDIM];
__device__ __align__(128) __half g_Xh[(size_t)BATCH * DDIM];
__device__ __align__(128) __half g_H1h[(size_t)BATCH * DDIM];
__device__ __align__(128) __half g_H2h[(size_t)BATCH * DDIM];
__device__ float g_B1[DDIM];
__device__ float g_B2[DDIM];
__device__ float g_B3[DDIM];

// ---------------------------------------------------------------------------
// Radix select v3 (R11/R12-verified): 12-bit plain-atomic hist (1 full pass)
// + compact (1 full pass) + cheap candidate-set passes for remaining 20 bits.
// key = (u & 0x80000000) ? ~u : (u | 0x80000000)   (ascending float order)
// ---------------------------------------------------------------------------
__device__ __forceinline__ unsigned int f2key(float f)
{
    unsigned int u = __float_as_uint(f);
    return (u & 0x80000000u) ? ~u : (u | 0x80000000u);
}

__global__ void rs_init(unsigned int k)
{
    int t = threadIdx.x;   // 1024
    if (t < 256) g_hist[t] = 0u;
    for (int i = t; i < 4096; i += 1024) g_hist12[i] = 0u;
    if (t == 0) { g_prefix = 0u; g_krem = k; g_cand_cnt = 0u; }
}

__global__ void rs_hist12(const float* __restrict__ p, int n4)
{
    __shared__ unsigned int sh[4096];
    for (int i = threadIdx.x; i < 4096; i += blockDim.x) sh[i] = 0u;
    __syncthreads();
    const float4* __restrict__ p4 = (const float4*)p;
    int i = blockIdx.x * blockDim.x + threadIdx.x;
    const int stride = gridDim.x * blockDim.x;
    for (; i < n4; i += stride) {
        float4 v = p4[i];
        atomicAdd(&sh[f2key(v.x) >> 20], 1u);
        atomicAdd(&sh[f2key(v.y) >> 20], 1u);
        atomicAdd(&sh[f2key(v.z) >> 20], 1u);
        atomicAdd(&sh[f2key(v.w) >> 20], 1u);
    }
    __syncthreads();
    for (int i2 = threadIdx.x; i2 < 4096; i2 += blockDim.x) {
        unsigned int cv = sh[i2];
        if (cv) atomicAdd(&g_hist12[i2], cv);
    }
}

__global__ void rs_scan4096(int shift)
{
    __shared__ unsigned int s[1024];
    const int t = threadIdx.x;   // 1024
    unsigned int c0 = g_hist12[4 * t + 0];
    unsigned int c1 = g_hist12[4 * t + 1];
    unsigned int c2 = g_hist12[4 * t + 2];
    unsigned int c3 = g_hist12[4 * t + 3];
    g_hist12[4 * t + 0] = 0u; g_hist12[4 * t + 1] = 0u;
    g_hist12[4 * t + 2] = 0u; g_hist12[4 * t + 3] = 0u;
    const unsigned int sum = c0 + c1 + c2 + c3;
    s[t] = sum;
    __syncthreads();
    #pragma unroll
    for (int off = 1; off < 1024; off <<= 1) {
        unsigned int add = (t >= off) ? s[t - off] : 0u;
        __syncthreads();
        s[t] += add;
        __syncthreads();
    }
    const unsigned int inc = s[t];
    const unsigned int exc = inc - sum;
    const unsigned int k   = g_krem;
    if (k >= exc && k < inc) {
        unsigned int run = exc, bin;
        if      (k < run + c0) { bin = 4u * t + 0u; }
        else if (k < (run += c0) + c1) { bin = 4u * t + 1u; }
        else if (k < (run += c1) + c2) { bin = 4u * t + 2u; }
        else    { run += c2;    bin = 4u * t + 3u; }
        g_prefix |= bin << shift;
        g_krem    = k - run;
    }
}

__global__ void rs_compact(const float* __restrict__ p, int n4)
{
    const unsigned int pref12 = g_prefix >> 20;
    const float4* __restrict__ p4 = (const float4*)p;
    const int stride = gridDim.x * blockDim.x;
    int i = blockIdx.x * blockDim.x + threadIdx.x;
    const int lane = threadIdx.x & 31;
    for (; i < n4; i += 2 * stride) {
        float4 v0 = p4[i];
        const bool has2 = (i + stride) < n4;
        float4 v1 = has2 ? p4[i + stride] : make_float4(0, 0, 0, 0);
        float arr[8] = {v0.x, v0.y, v0.z, v0.w, v1.x, v1.y, v1.z, v1.w};
        const int cnt = has2 ? 8 : 4;
        for (int c = 0; c < cnt; c++) {
            unsigned int key = f2key(arr[c]);
            bool m = (key >> 20) == pref12;
            unsigned int amask = __activemask();
            unsigned int bal = __ballot_sync(amask, m);
            if (m) {
                int leader = __ffs(bal) - 1;
                unsigned int base = 0;
                if (lane == leader)
                    base = atomicAdd(&g_cand_cnt, (unsigned int)__popc(bal));
                base = __shfl_sync(bal, base, leader);
                unsigned int idx = base + __popc(bal & ((1u << lane) - 1u));
                if (idx < CAND_CAP) g_cand[idx] = key;
            }
        }
    }
}

__global__ void rs_hist12c()
{
    __shared__ unsigned int sh[4096];
    for (int i = threadIdx.x; i < 4096; i += blockDim.x) sh[i] = 0u;
    __syncthreads();
    unsigned int n = g_cand_cnt;
    if (n > CAND_CAP) n = CAND_CAP;
    unsigned int i = blockIdx.x * blockDim.x + threadIdx.x;
    const unsigned int stride = gridDim.x * blockDim.x;
    for (; i < n; i += stride)
        atomicAdd(&sh[(g_cand[i] >> 8) & 0xFFFu], 1u);
    __syncthreads();
    for (int i2 = threadIdx.x; i2 < 4096; i2 += blockDim.x) {
        unsigned int cv = sh[i2];
        if (cv) atomicAdd(&g_hist12[i2], cv);
    }
}

__global__ void rs_histD()
{
    __shared__ unsigned int sh[256];
    for (int i = threadIdx.x; i < 256; i += blockDim.x) sh[i] = 0u;
    __syncthreads();
    const unsigned int pref24 = g_prefix >> 8;
    unsigned int n = g_cand_cnt;
    if (n > CAND_CAP) n = CAND_CAP;
    unsigned int i = blockIdx.x * blockDim.x + threadIdx.x;
    const unsigned int stride = gridDim.x * blockDim.x;
    for (; i < n; i += stride) {
        unsigned int key = g_cand[i];
        if ((key >> 8) == pref24) atomicAdd(&sh[key & 0xffu], 1u);
    }
    __syncthreads();
    for (int i2 = threadIdx.x; i2 < 256; i2 += blockDim.x) {
        unsigned int cv = sh[i2];
        if (cv) atomicAdd(&g_hist[i2], cv);
    }
}

__global__ void rs_pick()
{
    if (threadIdx.x == 0) {
        const unsigned int k = g_krem;
        unsigned int run = 0;
        for (int b = 0; b < 256; b++) {
            unsigned int c = g_hist[b];
            if (k < run + c) {
                unsigned int key = g_prefix | (unsigned int)b;
                unsigned int u = (key & 0x80000000u) ? (key ^ 0x80000000u) : ~key;
                g_thr = __uint_as_float(u);
                break;
            }
            run += c;
        }
    }
}

// ---------------------------------------------------------------------------
// mask / convert kernels (all fp16 single precision now)
// ---------------------------------------------------------------------------
__global__ void mask_half(const float* __restrict__ w,
                          const float* __restrict__ s,
                          __half* __restrict__ out, int n4)
{
    const float thr = g_thr;
    const float4* __restrict__ w4 = (const float4*)w;
    const float4* __restrict__ s4 = (const float4*)s;
    uint2* __restrict__ o2 = (uint2*)out;
    int i = blockIdx.x * blockDim.x + threadIdx.x;
    const int stride = gridDim.x * blockDim.x;
    for (; i < n4; i += stride) {
        float4 wv = w4[i];
        float4 sv = s4[i];
        float f0 = (sv.x >= thr) ? wv.x : 0.0f;
        float f1 = (sv.y >= thr) ? wv.y : 0.0f;
        float f2 = (sv.z >= thr) ? wv.z : 0.0f;
        float f3 = (sv.w >= thr) ? wv.w : 0.0f;
        uint2 o;
        o.x = (unsigned int)__half_as_ushort(__float2half_rn(f0)) |
              ((unsigned int)__half_as_ushort(__float2half_rn(f1)) << 16);
        o.y = (unsigned int)__half_as_ushort(__float2half_rn(f2)) |
              ((unsigned int)__half_as_ushort(__float2half_rn(f3)) << 16);
        o2[i] = o;
    }
}

__global__ void conv_half(const float* __restrict__ in,
                          __half* __restrict__ out, int n4)
{
    const float4* __restrict__ p4 = (const float4*)in;
    uint2* __restrict__ o2 = (uint2*)out;
    int i = blockIdx.x * blockDim.x + threadIdx.x;
    const int stride = gridDim.x * blockDim.x;
    for (; i < n4; i += stride) {
        float4 v = p4[i];
        uint2 o;
        o.x = (unsigned int)__half_as_ushort(__float2half_rn(v.x)) |
              ((unsigned int)__half_as_ushort(__float2half_rn(v.y)) << 16);
        o.y = (unsigned int)__half_as_ushort(__float2half_rn(v.z)) |
              ((unsigned int)__half_as_ushort(__float2half_rn(v.w)) << 16);
        o2[i] = o;
    }
}

__global__ void mask_mul(const float* __restrict__ w,
                         const float* __restrict__ s,
                         float* __restrict__ out, int n4)
{
    const float thr = g_thr;
    const float4* __restrict__ w4 = (const float4*)w;
    const float4* __restrict__ s4 = (const float4*)s;
    float4* __restrict__ o4 = (float4*)out;
    int i = blockIdx.x * blockDim.x + threadIdx.x;
    const int stride = gridDim.x * blockDim.x;
    for (; i < n4; i += stride) {
        float4 wv = w4[i];
        float4 sv = s4[i];
        float4 r;
        r.x = (sv.x >= thr) ? wv.x : 0.0f;
        r.y = (sv.y >= thr) ? wv.y : 0.0f;
        r.z = (sv.z >= thr) ? wv.z : 0.0f;
        r.w = (sv.w >= thr) ? wv.w : 0.0f;
        o4[i] = r;
    }
}

// ---------------------------------------------------------------------------
// cp.async + ldmatrix + mma.sync (fp16)
// ---------------------------------------------------------------------------
__device__ __forceinline__ uint32_t smem_u32(const void* p)
{
    uint32_t a;
    asm("{ .reg .u64 t; cvta.to.shared.u64 t, %1; cvt.u32.u64 %0, t; }"
        : "=r"(a) : "l"(p));
    return a;
}

__device__ __forceinline__ void cpasync16(uint32_t dst, const void* src)
{
    asm volatile("cp.async.cg.shared.global [%0], [%1], 16;"
                 :: "r"(dst), "l"(src) : "memory");
}
#define CP_COMMIT() asm volatile("cp.async.commit_group;" ::: "memory")
#define CP_WAIT_2() asm volatile("cp.async.wait_group 2;" ::: "memory")

__device__ __forceinline__ void ldsm4(uint32_t& r0, uint32_t& r1,
                                      uint32_t& r2, uint32_t& r3, uint32_t a)
{
    asm volatile("ldmatrix.sync.aligned.m8n8.x4.shared.b16 {%0,%1,%2,%3}, [%4];"
                 : "=r"(r0), "=r"(r1), "=r"(r2), "=r"(r3) : "r"(a));
}

__device__ __forceinline__ void mma16816h(float* c,
                                          uint32_t a0, uint32_t a1,
                                          uint32_t a2, uint32_t a3,
                                          uint32_t b0, uint32_t b1)
{
    asm volatile(
        "mma.sync.aligned.m16n8k16.row.col.f32.f16.f16.f32 "
        "{%0,%1,%2,%3}, {%4,%5,%6,%7}, {%8,%9}, {%0,%1,%2,%3};"
        : "+f"(c[0]), "+f"(c[1]), "+f"(c[2]), "+f"(c[3])
        : "r"(a0), "r"(a1), "r"(a2), "r"(a3), "r"(b0), "r"(b1));
}

// ---------------------------------------------------------------------------
// fp16 single-pass HMMA GEMM: C = A@B^T + bias (opt ReLU)
// A, B single fp16 (K-contig). 4-stage cp.async (prefetch depth 2);
// 2 CTAs/SM. Warp layout 4(M) x 2(N), warp tile 32x64 (R12-verified mapping).
// Stage: A[128][32] @0 (8KB), B[128][32] @8192 (8KB) -> 16 KB/stage.
// ---------------------------------------------------------------------------
#define BM 128
#define BN 128
#define BK 32
#define GSTAGES 4
#define STG_B (2 * BM * BK * 2)        /* 16384 bytes per stage */
#define GSMEM  (GSTAGES * STG_B)       /* 65536 */

template<int RELU, int OUT_HALF>
__global__ void __launch_bounds__(256, 2) gemm_hmma(
    const __half* __restrict__ A,
    const __half* __restrict__ B,
    const float* __restrict__ bias,
    float* __restrict__ outf,
    __half* __restrict__ outh)
{
    extern __shared__ __align__(128) char smem[];
    const uint32_t sbase = smem_u32(smem);
    const int tid  = threadIdx.x;
    const int lane = tid & 31;
    const int wid  = tid >> 5;
    const int wm   = wid >> 1;          // 0..3  (M group, 32 rows each)
    const int wn   = wid & 1;           // 0..1  (N group, 64 cols each)
    const int bx   = blockIdx.x;        // N tile
    const int by   = blockIdx.y;        // M tile
    const int K    = DDIM;

    const int lrow = tid >> 2;          // 0..63
    const int lch  = tid & 3;           // 16B chunk within 64B row
    const uint32_t d0 = (uint32_t)lrow * 64 + (uint32_t)((lch ^ (lrow & 3)) << 4);

    const int rowA = by * BM;
    const int rowB = bx * BN;
    const __half* sA0 = A + (size_t)(rowA + lrow) * K + lch * 8;
    const __half* sA1 = A + (size_t)(rowA + lrow + 64) * K + lch * 8;
    const __half* sB0 = B + (size_t)(rowB + lrow) * K + lch * 8;
    const __half* sB1 = B + (size_t)(rowB + lrow + 64) * K + lch * 8;

    #define LOAD_STAGE(stg, kt) do {                                          \
        const uint32_t s0 = sbase + (uint32_t)(stg) * STG_B + d0;             \
        const size_t ko = (size_t)(kt) * BK;                                  \
        cpasync16(s0,          sA0 + ko);                                     \
        cpasync16(s0 + 4096,   sA1 + ko);                                     \
        cpasync16(s0 + 8192,   sB0 + ko);                                     \
        cpasync16(s0 + 12288,  sB1 + ko);                                     \
    } while (0)

    float c[2][8][4];
    #pragma unroll
    for (int i = 0; i < 2; i++)
        #pragma unroll
        for (int j = 0; j < 8; j++)
            #pragma unroll
            for (int q = 0; q < 4; q++) c[i][j][q] = 0.0f;

    const int NT = K / BK;              // 128

    LOAD_STAGE(0, 0); CP_COMMIT();
    LOAD_STAGE(1, 1); CP_COMMIT();
    LOAD_STAGE(2, 2); CP_COMMIT();

    const int fr = lane & 15;
    const int fh = lane >> 4;

    for (int t = 0; t < NT; t++) {
        CP_WAIT_2();
        __syncthreads();

        const int lt = t + GSTAGES - 1;
        if (lt < NT) LOAD_STAGE(lt % GSTAGES, lt);
        CP_COMMIT();

        const uint32_t sb = sbase + (uint32_t)(t % GSTAGES) * STG_B;

        #pragma unroll
        for (int kk = 0; kk < 2; kk++) {
            const int chb = kk * 2 + fh;

            uint32_t aoff[2], boff[4];
            #pragma unroll
            for (int mi = 0; mi < 2; mi++) {
                const int row = wm * 32 + mi * 16 + fr;
                aoff[mi] = (uint32_t)row * 64 + (uint32_t)((chb ^ (row & 3)) << 4);
            }
            #pragma unroll
            for (int nj = 0; nj < 4; nj++) {
                const int row = wn * 64 + nj * 16 + fr;
                boff[nj] = (uint32_t)row * 64 + (uint32_t)((chb ^ (row & 3)) << 4);
            }

            uint32_t b[4][4];
            #pragma unroll
            for (int nj = 0; nj < 4; nj++)
                ldsm4(b[nj][0], b[nj][1], b[nj][2], b[nj][3],
                      sb + 8192u + boff[nj]);

            #pragma unroll
            for (int mi = 0; mi < 2; mi++) {
                uint32_t a0, a1, a2, a3;
                ldsm4(a0, a1, a2, a3, sb + aoff[mi]);
                #pragma unroll
                for (int nj = 0; nj < 4; nj++) {
                    mma16816h(c[mi][2 * nj + 0], a0, a1, a2, a3,
                              b[nj][0], b[nj][2]);
                    mma16816h(c[mi][2 * nj + 1], a0, a1, a2, a3,
                              b[nj][1], b[nj][3]);
                }
            }
        }
    }

    // --- epilogue: bias (+ReLU), then fp32 store or fp16 store ---
    const int q   = lane >> 2;          // 0..7
    const int rp  = lane & 3;           // column pair
    const int m0g = by * BM + wm * 32;
    const int n0g = bx * BN + wn * 64;

    #pragma unroll
    for (int mi = 0; mi < 2; mi++) {
        #pragma unroll
        for (int ni = 0; ni < 8; ni++) {
            const int col = n0g + ni * 8 + rp * 2;
            const float bv0 = __ldg(bias + col);
            const float bv1 = __ldg(bias + col + 1);
            float v0 = c[mi][ni][0] + bv0;
            float v1 = c[mi][ni][1] + bv1;
            float v2 = c[mi][ni][2] + bv0;
            float v3 = c[mi][ni][3] + bv1;
            if (RELU) {
                v0 = fmaxf(v0, 0.0f); v1 = fmaxf(v1, 0.0f);
                v2 = fmaxf(v2, 0.0f); v3 = fmaxf(v3, 0.0f);
            }
            const int r0 = m0g + mi * 16 + q;
            const int r1 = r0 + 8;
            if (OUT_HALF) {
                unsigned int h0 =
                    (unsigned int)__half_as_ushort(__float2half_rn(v0)) |
                    ((unsigned int)__half_as_ushort(__float2half_rn(v1)) << 16);
                unsigned int h1 =
                    (unsigned int)__half_as_ushort(__float2half_rn(v2)) |
                    ((unsigned int)__half_as_ushort(__float2half_rn(v3)) << 16);
                *(unsigned int*)(outh + (size_t)r0 * DDIM + col) = h0;
                *(unsigned int*)(outh + (size_t)r1 * DDIM + col) = h1;
            } else {
                *(float2*)(outf + (size_t)r0 * DDIM + col) = make_float2(v0, v1);
                *(float2*)(outf + (size_t)r1 * DDIM + col) = make_float2(v2, v3);
            }
        }
    }
    #undef LOAD_STAGE
}

// ---------------------------------------------------------------------------
// kernel_launch
// ---------------------------------------------------------------------------
extern "C" void kernel_launch(void* const* d_in, const int* in_sizes, int n_in,
                              void* d_out, int out_size)
{
    const float* x   = (const float*)d_in[0];
    const float* w1  = (const float*)d_in[1];
    const float* b1  = (const float*)d_in[2];
    const float* w2  = (const float*)d_in[3];
    const float* b2  = (const float*)d_in[4];
    const float* w3  = (const float*)d_in[5];
    const float* b3  = (const float*)d_in[6];
    const float* sw1 = (const float*)d_in[7];
    const float* sb1 = (const float*)d_in[8];
    const float* sw2 = (const float*)d_in[9];
    const float* sb2 = (const float*)d_in[10];
    const float* sw3 = (const float*)d_in[11];
    const float* sb3 = (const float*)d_in[12];
    float* out = (float*)d_out;

    const int M = in_sizes[0] / DDIM;   // 2048

    long long total = 0;
    for (int i = 7; i <= 12; i++) total += (long long)in_sizes[i];
    const unsigned int j = (unsigned int)(total / 2);

    const int nW4 = (DDIM * DDIM) / 4;
    const int nB4 = DDIM / 4;
    const int nX4 = (M * DDIM) / 4;

    // --- 1) exact global threshold: 12-bit hist + compact + tail passes ---
    rs_init<<<1, 1024>>>(j);
    rs_hist12<<<1024, 256>>>(sw1, nW4);
    rs_hist12<<<1024, 256>>>(sw2, nW4);
    rs_hist12<<<1024, 256>>>(sw3, nW4);
    rs_hist12<<<4,    256>>>(sb1, nB4);
    rs_hist12<<<4,    256>>>(sb2, nB4);
    rs_hist12<<<4,    256>>>(sb3, nB4);
    rs_scan4096<<<1, 1024>>>(20);
    rs_compact<<<1024, 256>>>(sw1, nW4);
    rs_compact<<<1024, 256>>>(sw2, nW4);
    rs_compact<<<1024, 256>>>(sw3, nW4);
    rs_compact<<<4,    256>>>(sb1, nB4);
    rs_compact<<<4,    256>>>(sb2, nB4);
    rs_compact<<<4,    256>>>(sb3, nB4);
    rs_hist12c<<<256, 256>>>();
    rs_scan4096<<<1, 1024>>>(8);
    rs_histD<<<64, 256>>>();
    rs_pick<<<1, 32>>>();

    // --- scratch symbol addresses ---
    __half *pW1, *pW2, *pW3, *pXh, *pH1h, *pH2h;
    float *pB1, *pB2, *pB3;
    cudaGetSymbolAddress((void**)&pW1,  g_W1h);
    cudaGetSymbolAddress((void**)&pW2,  g_W2h);
    cudaGetSymbolAddress((void**)&pW3,  g_W3h);
    cudaGetSymbolAddress((void**)&pXh,  g_Xh);
    cudaGetSymbolAddress((void**)&pH1h, g_H1h);
    cudaGetSymbolAddress((void**)&pH2h, g_H2h);
    cudaGetSymbolAddress((void**)&pB1,  g_B1);
    cudaGetSymbolAddress((void**)&pB2,  g_B2);
    cudaGetSymbolAddress((void**)&pB3,  g_B3);

    // --- 2) masked weights -> fp16 ; masked biases fp32 ; convert x ---
    mask_half<<<1024, 256>>>(w1, sw1, pW1, nW4);
    mask_half<<<1024, 256>>>(w2, sw2, pW2, nW4);
    mask_half<<<1024, 256>>>(w3, sw3, pW3, nW4);
    mask_mul<<<4, 256>>>(b1, sb1, pB1, nB4);
    mask_mul<<<4, 256>>>(b2, sb2, pB2, nB4);
    mask_mul<<<4, 256>>>(b3, sb3, pB3, nB4);
    conv_half<<<1024, 256>>>(x, pXh, nX4);

    // --- 3) three dependent single-pass fp16 HMMA GEMMs ---
    cudaFuncSetAttribute(gemm_hmma<1, 1>,
                         cudaFuncAttributeMaxDynamicSharedMemorySize, GSMEM);
    cudaFuncSetAttribute(gemm_hmma<0, 0>,
                         cudaFuncAttributeMaxDynamicSharedMemorySize, GSMEM);

    dim3 grid(DDIM / BN, M / BM);       // (32, 16)
    gemm_hmma<1, 1><<<grid, 256, GSMEM>>>(pXh,  pW1, pB1, nullptr, pH1h);
    gemm_hmma<1, 1><<<grid, 256, GSMEM>>>(pH1h, pW2, pB2, nullptr, pH2h);
    gemm_hmma<0, 0><<<grid, 256, GSMEM>>>(pH2h, pW3, pB3, out, nullptr);

    (void)n_in; (void)out_size;
}